// round 12
// baseline (speedup 1.0000x reference)
#include <cuda_runtime.h>
#include <math.h>

#define NN 5000
#define NE 60000
#define NT 400000

// ---------------- scratch (device globals) --------------------------------------
__device__ float g_bondvec[NE * 3];
__device__ float g_dist[NE];
__device__ float g_rbf[NE * 9];
__device__ float g_cut3[NE];
__device__ float g_tbw[NT * 9];
__device__ int   g_endatom[NT];
__device__ float g_nodefeat[NN * 128];
__device__ float g_edgefeat[NE * 128];
__device__ float g_atoms[NN * 9];
__device__ float g_nb[NE * 9];
__device__ float g_nodepre[8 * NN * 128];   // slices: br*4 + chain*2 + side
__device__ float g_mean[128];
__device__ unsigned g_wbf16[6 * 6 * 128 * 64];  // [kbr][layer:{h0e,h1,h2,g0e,g1,g2}][128][64w]

struct Scales { float v[9]; };

__constant__ float c_roots[9] = {
    3.141592653589793f, 6.283185307179586f, 9.42477796076938f,
    4.493409457909064f, 7.725251836937707f, 10.904121659428899f,
    5.763459196894550f, 9.095011330476355f, 12.322940970566582f};

#define Y00F 0.28209479177387814f
#define Y10F 0.4886025119029199f
#define Y20F 0.31539156525252005f

__device__ __forceinline__ float siluf(float v) { return v / (1.f + expf(-v)); }
__device__ __forceinline__ float sigf(float v)  { return 1.f / (1.f + expf(-v)); }

__device__ __forceinline__ float jlf(int l, float x) {
    float s, c;
    sincosf(x, &s, &c);
    float inv = 1.f / x;
    if (l == 0) return s * inv;
    if (l == 1) return (s * inv - c) * inv;
    return (3.f * inv * inv - 1.f) * s * inv - 3.f * c * inv * inv;
}

// ---------------- mma / pack primitives -----------------------------------------
__device__ __forceinline__ unsigned f2tf(float x) {
    unsigned u;
    asm("cvt.rna.tf32.f32 %0, %1;" : "=r"(u) : "f"(x));
    return u;
}
__device__ __forceinline__ void mma_tf32(float* d, const unsigned* a, unsigned b0, unsigned b1) {
    asm volatile(
        "mma.sync.aligned.m16n8k8.row.col.f32.tf32.tf32.f32 "
        "{%0,%1,%2,%3}, {%4,%5,%6,%7}, {%8,%9}, {%0,%1,%2,%3};"
        : "+f"(d[0]), "+f"(d[1]), "+f"(d[2]), "+f"(d[3])
        : "r"(a[0]), "r"(a[1]), "r"(a[2]), "r"(a[3]), "r"(b0), "r"(b1));
}
__device__ __forceinline__ unsigned pack_bf16(float lo, float hi) {
    unsigned r;
    asm("cvt.rn.bf16x2.f32 %0, %1, %2;" : "=r"(r) : "f"(hi), "f"(lo));
    return r;
}
__device__ __forceinline__ float bf_lo(unsigned p) { return __uint_as_float(p << 16); }
__device__ __forceinline__ float bf_hi(unsigned p) { return __uint_as_float(p & 0xffff0000u); }
__device__ __forceinline__ void ldm_x4(unsigned& r0, unsigned& r1, unsigned& r2, unsigned& r3,
                                       unsigned addr) {
    asm volatile("ldmatrix.sync.aligned.m8n8.x4.shared.b16 {%0,%1,%2,%3}, [%4];"
                 : "=r"(r0), "=r"(r1), "=r"(r2), "=r"(r3) : "r"(addr));
}
__device__ __forceinline__ void ldm_x4_t(unsigned& r0, unsigned& r1, unsigned& r2, unsigned& r3,
                                         unsigned addr) {
    asm volatile("ldmatrix.sync.aligned.m8n8.x4.trans.shared.b16 {%0,%1,%2,%3}, [%4];"
                 : "=r"(r0), "=r"(r1), "=r"(r2), "=r"(r3) : "r"(addr));
}
__device__ __forceinline__ void mma_bf16(float* d, const unsigned* a, unsigned b0, unsigned b1) {
    asm volatile(
        "mma.sync.aligned.m16n8k16.row.col.f32.bf16.bf16.f32 "
        "{%0,%1,%2,%3}, {%4,%5,%6,%7}, {%8,%9}, {%0,%1,%2,%3};"
        : "+f"(d[0]), "+f"(d[1]), "+f"(d[2]), "+f"(d[3])
        : "r"(a[0]), "r"(a[1]), "r"(a[2]), "r"(a[3]), "r"(b0), "r"(b1));
}

// ---------------- weight pre-conversion (fp32 -> bf16x2) ------------------------
__global__ void k_convw(const float* __restrict__ W0, const float* __restrict__ W1,
                        const float* __restrict__ W2, const float* __restrict__ gW0,
                        const float* __restrict__ gW1, const float* __restrict__ gW2) {
    int idx = blockIdx.x * blockDim.x + threadIdx.x;
    if (idx >= 6 * 6 * 8192) return;
    int kbr = idx / 49152;
    int rem = idx - kbr * 49152;
    int l = rem / 8192;
    int pos = rem - l * 8192;
    int row = pos >> 6, cw = pos & 63;
    const float* src;
    if (l == 0)      src = W0  + (size_t)kbr * 384 * 128 + 256 * 128;
    else if (l == 1) src = W1  + (size_t)kbr * 128 * 128;
    else if (l == 2) src = W2  + (size_t)kbr * 128 * 128;
    else if (l == 3) src = gW0 + (size_t)kbr * 384 * 128 + 256 * 128;
    else if (l == 4) src = gW1 + (size_t)kbr * 128 * 128;
    else             src = gW2 + (size_t)kbr * 128 * 128;
    float2 v = *(const float2*)(src + row * 128 + cw * 2);
    g_wbf16[idx] = pack_bf16(v.x, v.y);
}

// ---------------- kernel 0: geom + nodeinit + zero mean -------------------------
__global__ void k_setup0(const float* __restrict__ pos, const int* __restrict__ src,
                         const int* __restrict__ dst, const int* __restrict__ node_type,
                         const float* __restrict__ emb, Scales sc) {
    int idx = blockIdx.x * blockDim.x + threadIdx.x;
    if (idx < NE) {
        int e = idx;
        int s = src[e], d = dst[e];
        float dx = pos[d * 3 + 0] - pos[s * 3 + 0];
        float dy = pos[d * 3 + 1] - pos[s * 3 + 1];
        float dz = pos[d * 3 + 2] - pos[s * 3 + 2];
        float dist = sqrtf(dx * dx + dy * dy + dz * dz + 1e-12f);
        g_bondvec[e * 3 + 0] = dx;
        g_bondvec[e * 3 + 1] = dy;
        g_bondvec[e * 3 + 2] = dz;
        g_dist[e] = dist;
#pragma unroll
        for (int l = 0; l < 3; l++)
#pragma unroll
            for (int n = 0; n < 3; n++)
                g_rbf[e * 9 + l * 3 + n] = jlf(l, dist * c_roots[l * 3 + n] * 0.2f) * sc.v[l * 3 + n];
        float xx = dist * 0.25f;
        float x2 = xx * xx, x3 = x2 * xx;
        g_cut3[e] = 1.f - 6.f * x3 * x2 + 15.f * x2 * x2 - 10.f * x3;
    } else if (idx < NE + NN * 128) {
        int i = idx - NE;
        int n = i >> 7, c = i & 127;
        g_nodefeat[i] = emb[node_type[n] * 128 + c];
    } else if (idx < NE + NN * 128 + 128) {
        g_mean[idx - NE - NN * 128] = 0.f;
    }
}

// ---------------- kernel 1: triplet + edgeemb -----------------------------------
__global__ void k_setup1(const int* __restrict__ t_src, const int* __restrict__ t_dst,
                         const int* __restrict__ dst,
                         const float* __restrict__ W, const float* __restrict__ b) {
    int idx = blockIdx.x * blockDim.x + threadIdx.x;
    if (idx < NT) {
        int t = idx;
        int es = t_src[t], ed = t_dst[t];
        float v1x = g_bondvec[es * 3 + 0], v1y = g_bondvec[es * 3 + 1], v1z = g_bondvec[es * 3 + 2];
        float v2x = g_bondvec[ed * 3 + 0], v2y = g_bondvec[ed * 3 + 1], v2z = g_bondvec[ed * 3 + 2];
        float cost = (v1x * v2x + v1y * v2y + v1z * v2z) / (g_dist[es] * g_dist[ed]);
        float shf0 = Y00F;
        float shf1 = Y10F * cost;
        float shf2 = Y20F * (3.f * cost * cost - 1.f);
        float tw = g_cut3[es] * g_cut3[ed];
#pragma unroll
        for (int n = 0; n < 3; n++) {
            g_tbw[t * 9 + n]     = g_rbf[ed * 9 + n] * shf0 * tw;
            g_tbw[t * 9 + 3 + n] = g_rbf[ed * 9 + 3 + n] * shf1 * tw;
            g_tbw[t * 9 + 6 + n] = g_rbf[ed * 9 + 6 + n] * shf2 * tw;
        }
        g_endatom[t] = dst[ed];
    } else if (idx < NT + NE * 128) {
        int i = idx - NT;
        int e = i >> 7, j = i & 127;
        float acc = b[j];
#pragma unroll
        for (int q = 0; q < 9; q++) acc = fmaf(g_rbf[e * 9 + q], W[q * 128 + j], acc);
        g_edgefeat[i] = siluf(acc);
    }
}

// ---------------- kernel 2: nodegemm(8 slices, tf32) + atoms + zero_nb ----------
#define NG_BLOCKS 320
#define AT_BLOCKS 176
#define ZB_BLOCKS 2110

__global__ void __launch_bounds__(256) k_block_setup(
    const float* __restrict__ W0, const float* __restrict__ gW0,
    const float* __restrict__ b0, const float* __restrict__ gb0,
    const float* __restrict__ taW, const float* __restrict__ tab, int k) {
    int blk = blockIdx.x;
    if (blk < NG_BLOCKS) {
        __shared__ unsigned sA[128 * 40];
        __shared__ unsigned sB[32 * 136];
        int slice = blk & 7, mt = blk >> 3;
        int br = slice >> 2, chain = (slice >> 1) & 1, side = slice & 1;
        const float* Wbase = (chain ? gW0 : W0) + (size_t)(k * 2 + br) * 384 * 128 + side * 128 * 128;
        const float* bias = side == 0 ? ((chain ? gb0 : b0) + (k * 2 + br) * 128) : nullptr;
        float* out = g_nodepre + (size_t)slice * NN * 128;
        const float* A = g_nodefeat;
        int bm = mt * 128;

        const int tid = threadIdx.x;
        const int lane = tid & 31, wid = tid >> 5;
        const int wm = (wid & 3) * 32, wn = (wid >> 2) * 64;
        float acc[2][8][4];
#pragma unroll
        for (int i = 0; i < 2; i++)
#pragma unroll
            for (int j = 0; j < 8; j++)
#pragma unroll
                for (int q = 0; q < 4; q++) acc[i][j][q] = 0.f;

        const int r0 = tid >> 3, c4 = tid & 7;
        const int bk0 = tid >> 5, bn4 = tid & 31;
        for (int kt = 0; kt < 4; kt++) {
#pragma unroll
            for (int i = 0; i < 4; i++) {
                int gm = bm + r0 + 32 * i;
                float4 v = make_float4(0.f, 0.f, 0.f, 0.f);
                if (gm < NN) v = *(const float4*)(A + (size_t)gm * 128 + kt * 32 + c4 * 4);
                uint4 u;
                u.x = f2tf(v.x); u.y = f2tf(v.y); u.z = f2tf(v.z); u.w = f2tf(v.w);
                *(uint4*)&sA[(r0 + 32 * i) * 40 + c4 * 4] = u;
            }
#pragma unroll
            for (int i = 0; i < 4; i++) {
                float4 v = *(const float4*)(Wbase + (size_t)(kt * 32 + bk0 + 8 * i) * 128 + bn4 * 4);
                uint4 u;
                u.x = f2tf(v.x); u.y = f2tf(v.y); u.z = f2tf(v.z); u.w = f2tf(v.w);
                *(uint4*)&sB[(bk0 + 8 * i) * 136 + bn4 * 4] = u;
            }
            __syncthreads();
#pragma unroll
            for (int ks = 0; ks < 4; ks++) {
                unsigned a[2][4];
                int arow = wm + (lane >> 2);
                int acol = ks * 8 + (lane & 3);
#pragma unroll
                for (int m2 = 0; m2 < 2; m2++) {
                    int rr = arow + m2 * 16;
                    a[m2][0] = sA[rr * 40 + acol];
                    a[m2][1] = sA[(rr + 8) * 40 + acol];
                    a[m2][2] = sA[rr * 40 + acol + 4];
                    a[m2][3] = sA[(rr + 8) * 40 + acol + 4];
                }
                int bro = (ks * 8 + (lane & 3)) * 136 + wn + (lane >> 2);
#pragma unroll
                for (int nt = 0; nt < 8; nt++) {
                    unsigned b0r = sB[bro + nt * 8];
                    unsigned b1r = sB[bro + 4 * 136 + nt * 8];
                    mma_tf32(acc[0][nt], a[0], b0r, b1r);
                    mma_tf32(acc[1][nt], a[1], b0r, b1r);
                }
            }
            __syncthreads();
        }
#pragma unroll
        for (int m2 = 0; m2 < 2; m2++) {
#pragma unroll
            for (int nt = 0; nt < 8; nt++) {
                int gn = wn + nt * 8 + 2 * (lane & 3);
                float bv0 = bias ? bias[gn] : 0.f;
                float bv1 = bias ? bias[gn + 1] : 0.f;
                int gm0 = bm + wm + m2 * 16 + (lane >> 2);
                if (gm0 < NN)
                    *(float2*)(out + (size_t)gm0 * 128 + gn) =
                        make_float2(acc[m2][nt][0] + bv0, acc[m2][nt][1] + bv1);
                int gm1 = gm0 + 8;
                if (gm1 < NN)
                    *(float2*)(out + (size_t)gm1 * 128 + gn) =
                        make_float2(acc[m2][nt][2] + bv0, acc[m2][nt][3] + bv1);
            }
        }
    } else if (blk < NG_BLOCKS + AT_BLOCKS) {
        int idx = (blk - NG_BLOCKS) * 256 + threadIdx.x;
        if (idx < NN * 9) {
            int n = idx / 9, j = idx % 9;
            float acc = tab[k * 9 + j];
            const float* nf = &g_nodefeat[n * 128];
            const float* W = taW + (size_t)k * 128 * 9;
#pragma unroll 8
            for (int i = 0; i < 128; i++) acc = fmaf(nf[i], W[i * 9 + j], acc);
            g_atoms[idx] = sigf(acc);
        }
    } else {
        int idx = (blk - NG_BLOCKS - AT_BLOCKS) * 256 + threadIdx.x;
        if (idx < NE * 9) g_nb[idx] = 0.f;
    }
}

// ---------------- tripacc --------------------------------------------------------
__global__ void k_tripacc(const int* __restrict__ t_src) {
    int t = blockIdx.x * blockDim.x + threadIdx.x;
    if (t >= NT) return;
    int es = t_src[t];
    int ea = g_endatom[t];
#pragma unroll
    for (int q = 0; q < 9; q++)
        atomicAdd(&g_nb[es * 9 + q], g_tbw[t * 9 + q] * g_atoms[ea * 9 + q]);
}

// ---------------- fused megakernel: BM=128, 512 threads, 1 CTA/SM ---------------
// smem bytes: sAct @0 (34816) | sAe @34816 (34816) | sB0 @69632 (17408) |
//             sB1 @87040 (17408) | sE f32 @104448 (69632) | swt @174080 (4608)
#define FUSED_SMEM 178688
#define FUSED_GRID ((NE + 127) / 128)
#define STR 136

__global__ void __launch_bounds__(512, 1) fused_block(
    const int* __restrict__ src, const int* __restrict__ dst,
    const float* __restrict__ Wbk, const float* __restrict__ Wgk,
    const unsigned* __restrict__ wbase,                 // bf16 weights, this k (2 branches)
    const float* __restrict__ b1k, const float* __restrict__ b2k,
    const float* __restrict__ gb1k, const float* __restrict__ gb2k,
    const float* __restrict__ wtk) {
    extern __shared__ char smem_raw[];
    unsigned* sActw = (unsigned*)(smem_raw);
    unsigned* sAew  = (unsigned*)(smem_raw + 34816);
    float*    sE    = (float*)(smem_raw + 104448);
    float*    swt   = (float*)(smem_raw + 174080);

    const unsigned act_u = (unsigned)__cvta_generic_to_shared(sActw);
    const unsigned ae_u  = (unsigned)__cvta_generic_to_shared(sAew);
    const unsigned b0_u  = (unsigned)__cvta_generic_to_shared(smem_raw + 69632);
    const unsigned b1_u  = (unsigned)__cvta_generic_to_shared(smem_raw + 87040);

    const int tid = threadIdx.x;
    const int lane = tid & 31, wid = tid >> 5;
    const int wm = (wid & 7) * 16, wn = (wid >> 3) * 64;
    const int bm = blockIdx.x * 128;

    const int rr0 = wm + (lane >> 2);
    const int e0 = bm + rr0, e1 = e0 + 8;
    const bool v0 = e0 < NE, v1 = e1 < NE;
    const int s0 = v0 ? src[e0] : 0, d0 = v0 ? dst[e0] : 0;
    const int s1 = v1 ? src[e1] : 0, d1 = v1 ? dst[e1] : 0;

    // ---- stage A: three-body edge update into sE -------------------------------
    {
        float* sWb = (float*)sActw;
        float* sWg = (float*)sAew;
        for (int i = tid; i < 9 * 128; i += 512) { sWb[i] = Wbk[i]; sWg[i] = Wgk[i]; }
        __syncthreads();
        for (int i = tid; i < 128 * 128; i += 512) {
            int row = i >> 7, col = i & 127;
            int e = bm + row;
            float val = 0.f;
            if (e < NE) {
                float s1v = 0.f, s2v = 0.f;
#pragma unroll
                for (int q = 0; q < 9; q++) {
                    float nv = g_nb[e * 9 + q];
                    s1v = fmaf(nv, sWb[q * 128 + col], s1v);
                    s2v = fmaf(nv, sWg[q * 128 + col], s2v);
                }
                val = g_edgefeat[(size_t)e * 128 + col] + siluf(s1v) * sigf(s2v);
            }
            sE[row * STR + col] = val;
        }
        __syncthreads();
    }

    float acc[8][4];
    unsigned hpk[8][2];   // silu(h2) packed bf16x2

    auto zero_acc = [&] {
#pragma unroll
        for (int j = 0; j < 8; j++)
#pragma unroll
            for (int q = 0; q < 4; q++) acc[j][q] = 0.f;
    };
    // async-copy one 64x128 bf16 weight slab (row stride 272B in smem)
    auto cp_slab = [&](const unsigned* Wb, int slab, unsigned bufu) {
#pragma unroll
        for (int i = 0; i < 2; i++) {
            int c = tid + 512 * i;
            int row = c >> 4, c4 = c & 15;
            unsigned dstb = bufu + (unsigned)(row * 272 + c4 * 16);
            const unsigned* srcp = Wb + (slab * 64 + row) * 64 + c4 * 4;
            asm volatile("cp.async.cg.shared.global [%0], [%1], 16;"
                         :: "r"(dstb), "l"(srcp) : "memory");
        }
        asm volatile("cp.async.commit_group;" ::: "memory");
    };
    auto compute_tile = [&](unsigned abase, unsigned bbase, int kbase) {
        unsigned a[4];
        {
            int arow = wm + (lane & 7) + ((lane >> 3) & 1) * 8;
            int acol = kbase + (lane >> 4) * 8;
            ldm_x4(a[0], a[1], a[2], a[3], abase + (unsigned)(arow * STR + acol) * 2);
        }
        int krow = (kbase & 63) + (lane & 15);
        int cofs = (lane >> 4) * 8;
#pragma unroll
        for (int j = 0; j < 4; j++) {
            unsigned b[4];
            int n0 = wn + 16 * j;
            ldm_x4_t(b[0], b[1], b[2], b[3], bbase + (unsigned)(krow * STR + n0 + cofs) * 2);
            mma_bf16(acc[2 * j], a, b[0], b[1]);
            mma_bf16(acc[2 * j + 1], a, b[2], b[3]);
        }
    };
    auto gemm_layer = [&](unsigned abase, const unsigned* Wb) {
        zero_acc();
        cp_slab(Wb, 0, b0_u);
        asm volatile("cp.async.wait_group 0;" ::: "memory");
        __syncthreads();
        cp_slab(Wb, 1, b1_u);
#pragma unroll
        for (int ks = 0; ks < 4; ks++) compute_tile(abase, b0_u, ks * 16);
        asm volatile("cp.async.wait_group 0;" ::: "memory");
        __syncthreads();
#pragma unroll
        for (int ks = 0; ks < 4; ks++) compute_tile(abase, b1_u, 64 + ks * 16);
        __syncthreads();
    };
    auto conv_sE = [&] {
        for (int i = tid; i < 128 * 64; i += 512) {
            int row = i >> 6, cp = i & 63;
            sAew[row * 68 + cp] = pack_bf16(sE[row * STR + 2 * cp], sE[row * STR + 2 * cp + 1]);
        }
    };

    // one gated-MLP chain; leaves final raw L2 pre-activation in acc.
    auto run_chain = [&](const unsigned* wch, const float* NS, const float* ND,
                         const float* b1v) {
        gemm_layer(ae_u, wch);                      // L0 (A = edge tile)
#pragma unroll
        for (int nt = 0; nt < 8; nt++) {
            int gn = wn + nt * 8 + 2 * (lane & 3);
            float2 ns0 = v0 ? *(const float2*)(NS + (size_t)s0 * 128 + gn) : make_float2(0, 0);
            float2 nd0 = v0 ? *(const float2*)(ND + (size_t)d0 * 128 + gn) : make_float2(0, 0);
            float2 ns1 = v1 ? *(const float2*)(NS + (size_t)s1 * 128 + gn) : make_float2(0, 0);
            float2 nd1 = v1 ? *(const float2*)(ND + (size_t)d1 * 128 + gn) : make_float2(0, 0);
            sActw[rr0 * 68 + (gn >> 1)] =
                pack_bf16(siluf(acc[nt][0] + ns0.x + nd0.x), siluf(acc[nt][1] + ns0.y + nd0.y));
            sActw[(rr0 + 8) * 68 + (gn >> 1)] =
                pack_bf16(siluf(acc[nt][2] + ns1.x + nd1.x), siluf(acc[nt][3] + ns1.y + nd1.y));
        }
        gemm_layer(act_u, wch + 8192);              // L1
#pragma unroll
        for (int nt = 0; nt < 8; nt++) {
            int gn = wn + nt * 8 + 2 * (lane & 3);
            float bv0 = b1v[gn], bv1 = b1v[gn + 1];
            sActw[rr0 * 68 + (gn >> 1)] =
                pack_bf16(siluf(acc[nt][0] + bv0), siluf(acc[nt][1] + bv1));
            sActw[(rr0 + 8) * 68 + (gn >> 1)] =
                pack_bf16(siluf(acc[nt][2] + bv0), siluf(acc[nt][3] + bv1));
        }
        gemm_layer(act_u, wch + 16384);             // L2 -> raw acc
    };

    for (int br = 0; br < 2; br++) {
        const unsigned* wbr = wbase + (size_t)br * 49152;
        const float* bh1 = b1k + br * 128;
        const float* bg1 = gb1k + br * 128;
        const float* bh2 = b2k + br * 128;
        const float* bg2 = gb2k + br * 128;
        const float* NSh = g_nodepre + (size_t)(br * 4 + 0) * NN * 128;
        const float* NDh = g_nodepre + (size_t)(br * 4 + 1) * NN * 128;
        const float* NSg = g_nodepre + (size_t)(br * 4 + 2) * NN * 128;
        const float* NDg = g_nodepre + (size_t)(br * 4 + 3) * NN * 128;

        conv_sE();
        for (int i = tid; i < 9 * 128; i += 512) swt[i] = wtk[br * 9 * 128 + i];
        // ordering provided by first gemm_layer's internal barrier

        // h chain -> pack silu(h2) to bf16x2
        run_chain(wbr, NSh, NDh, bh1);
#pragma unroll
        for (int nt = 0; nt < 8; nt++) {
            int gn = wn + nt * 8 + 2 * (lane & 3);
            float bv0 = bh2[gn], bv1 = bh2[gn + 1];
            hpk[nt][0] = pack_bf16(siluf(acc[nt][0] + bv0), siluf(acc[nt][1] + bv1));
            hpk[nt][1] = pack_bf16(siluf(acc[nt][2] + bv0), siluf(acc[nt][3] + bv1));
        }
        // g chain (raw L2 in acc)
        run_chain(wbr + 24576, NSg, NDg, bg1);

        // ---- epilogue ----
        float rb0[9], rb1[9];
#pragma unroll
        for (int q = 0; q < 9; q++) {
            rb0[q] = v0 ? g_rbf[e0 * 9 + q] : 0.f;
            rb1[q] = v1 ? g_rbf[e1 * 9 + q] : 0.f;
        }
#pragma unroll
        for (int nt = 0; nt < 8; nt++) {
            int gn = wn + nt * 8 + 2 * (lane & 3);
            float w00 = 0.f, w01 = 0.f, w10 = 0.f, w11 = 0.f;
#pragma unroll
            for (int q = 0; q < 9; q++) {
                float wc0 = swt[q * 128 + gn], wc1 = swt[q * 128 + gn + 1];
                w00 = fmaf(rb0[q], wc0, w00);
                w01 = fmaf(rb0[q], wc1, w01);
                w10 = fmaf(rb1[q], wc0, w10);
                w11 = fmaf(rb1[q], wc1, w11);
            }
            float gb0v = bg2[gn], gb1v = bg2[gn + 1];
            float val0 = bf_lo(hpk[nt][0]) * sigf(acc[nt][0] + gb0v) * w00;
            float val1 = bf_hi(hpk[nt][0]) * sigf(acc[nt][1] + gb1v) * w01;
            float val2 = bf_lo(hpk[nt][1]) * sigf(acc[nt][2] + gb0v) * w10;
            float val3 = bf_hi(hpk[nt][1]) * sigf(acc[nt][3] + gb1v) * w11;
            if (br == 0) {
                if (v0) {
                    float n0v = sE[rr0 * STR + gn] + val0;
                    float n1v = sE[rr0 * STR + gn + 1] + val1;
                    sE[rr0 * STR + gn] = n0v;
                    sE[rr0 * STR + gn + 1] = n1v;
                    *(float2*)(g_edgefeat + (size_t)e0 * 128 + gn) = make_float2(n0v, n1v);
                }
                if (v1) {
                    float n2v = sE[(rr0 + 8) * STR + gn] + val2;
                    float n3v = sE[(rr0 + 8) * STR + gn + 1] + val3;
                    sE[(rr0 + 8) * STR + gn] = n2v;
                    sE[(rr0 + 8) * STR + gn + 1] = n3v;
                    *(float2*)(g_edgefeat + (size_t)e1 * 128 + gn) = make_float2(n2v, n3v);
                }
            } else {
                if (v0) {
                    atomicAdd(&g_nodefeat[(size_t)d0 * 128 + gn], val0);
                    atomicAdd(&g_nodefeat[(size_t)d0 * 128 + gn + 1], val1);
                }
                if (v1) {
                    atomicAdd(&g_nodefeat[(size_t)d1 * 128 + gn], val2);
                    atomicAdd(&g_nodefeat[(size_t)d1 * 128 + gn + 1], val3);
                }
            }
        }
        __syncthreads();
    }
}

// ---------------- readout -------------------------------------------------------
__global__ void k_mean() {
    int j = threadIdx.x;
    int b = blockIdx.x;
    float s = 0.f;
    for (int n = b * 125; n < b * 125 + 125; n++) s += g_nodefeat[n * 128 + j];
    atomicAdd(&g_mean[j], s);
}

__global__ void k_final(const float* __restrict__ fW0, const float* __restrict__ fb0,
                        const float* __restrict__ fW1, const float* __restrict__ fb1,
                        const float* __restrict__ fW2, const float* __restrict__ fb2,
                        float* __restrict__ out) {
    __shared__ float v[128], h0[128], h1[128], red[128];
    int j = threadIdx.x;
    v[j] = g_mean[j] / (float)NN;
    __syncthreads();
    float a = fb0[j];
    for (int i = 0; i < 128; i++) a = fmaf(v[i], fW0[i * 128 + j], a);
    h0[j] = siluf(a);
    __syncthreads();
    a = fb1[j];
    for (int i = 0; i < 128; i++) a = fmaf(h0[i], fW1[i * 128 + j], a);
    h1[j] = siluf(a);
    __syncthreads();
    red[j] = h1[j] * fW2[j];
    __syncthreads();
    for (int st = 64; st > 0; st >>= 1) {
        if (j < st) red[j] += red[j + st];
        __syncthreads();
    }
    if (j == 0) out[0] = red[0] + fb2[0];
}

// ---------------- host ----------------------------------------------------------
static double h_jl(int l, double x) {
    double s = sin(x), c = cos(x);
    if (l == 1) return s / (x * x) - c / x;
    if (l == 2) return (3.0 / (x * x * x) - 1.0 / x) * s - 3.0 * c / (x * x);
    return (15.0 / (x * x * x * x) - 6.0 / (x * x)) * s - (15.0 / (x * x * x) - 1.0 / x) * c;
}

extern "C" void kernel_launch(void* const* d_in, const int* in_sizes, int n_in,
                              void* d_out, int out_size) {
    const float* pos  = (const float*)d_in[0];
    const int* node_type = (const int*)d_in[1];
    const int* src  = (const int*)d_in[2];
    const int* dst  = (const int*)d_in[3];
    const int* t_src = (const int*)d_in[4];
    const int* t_dst = (const int*)d_in[5];
    const float* emb  = (const float*)d_in[6];
    const float* eW   = (const float*)d_in[7];
    const float* eb   = (const float*)d_in[8];
    const float* taW  = (const float*)d_in[9];
    const float* tab  = (const float*)d_in[10];
    const float* tbW  = (const float*)d_in[11];
    const float* tbWg = (const float*)d_in[12];
    const float* W0 = (const float*)d_in[13];  const float* b0 = (const float*)d_in[14];
    const float* W1 = (const float*)d_in[15];  const float* b1 = (const float*)d_in[16];
    const float* W2 = (const float*)d_in[17];  const float* b2 = (const float*)d_in[18];
    const float* gW0 = (const float*)d_in[19]; const float* gb0 = (const float*)d_in[20];
    const float* gW1 = (const float*)d_in[21]; const float* gb1 = (const float*)d_in[22];
    const float* gW2 = (const float*)d_in[23]; const float* gb2 = (const float*)d_in[24];
    const float* wt = (const float*)d_in[25];
    const float* fW0 = (const float*)d_in[26]; const float* fb0 = (const float*)d_in[27];
    const float* fW1 = (const float*)d_in[28]; const float* fb1 = (const float*)d_in[29];
    const float* fW2 = (const float*)d_in[30]; const float* fb2 = (const float*)d_in[31];
    float* out = (float*)d_out;

    Scales sc;
    {
        const double roots[9] = {
            3.141592653589793, 6.283185307179586, 9.42477796076938,
            4.493409457909064, 7.725251836937707, 10.904121659428899,
            5.763459196894550, 9.095011330476355, 12.322940970566582};
        double fac = sqrt(2.0 / 125.0);
        for (int l = 0; l < 3; l++)
            for (int n = 0; n < 3; n++)
                sc.v[l * 3 + n] = (float)(fac / fabs(h_jl(l + 1, roots[l * 3 + n])));
    }

    unsigned* pwb;
    cudaGetSymbolAddress((void**)&pwb, g_wbf16);

    cudaFuncSetAttribute(fused_block, cudaFuncAttributeMaxDynamicSharedMemorySize, FUSED_SMEM);

    k_convw<<<(6 * 6 * 8192 + 255) / 256, 256>>>(W0, W1, W2, gW0, gW1, gW2);
    int n0 = NE + NN * 128 + 128;
    k_setup0<<<(n0 + 255) / 256, 256>>>(pos, src, dst, node_type, emb, sc);
    int n1 = NT + NE * 128;
    k_setup1<<<(n1 + 255) / 256, 256>>>(t_src, t_dst, dst, eW, eb);

    for (int k = 0; k < 3; k++) {
        k_block_setup<<<NG_BLOCKS + AT_BLOCKS + ZB_BLOCKS, 256>>>(W0, gW0, b0, gb0, taW, tab, k);
        k_tripacc<<<(NT + 255) / 256, 256>>>(t_src);
        fused_block<<<FUSED_GRID, 512, FUSED_SMEM>>>(
            src, dst, tbW + k * 9 * 128, tbWg + k * 9 * 128,
            pwb + (size_t)k * 2 * 49152,
            b1 + k * 2 * 128, b2 + k * 2 * 128,
            gb1 + k * 2 * 128, gb2 + k * 2 * 128,
            wt + k * 2 * 9 * 128);
    }
    k_mean<<<40, 128>>>();
    k_final<<<1, 128>>>(fW0, fb0, fW1, fb1, fW2, fb2, out);
}

// round 13
// speedup vs baseline: 1.0015x; 1.0015x over previous
#include <cuda_runtime.h>
#include <math.h>

#define NN 5000
#define NE 60000
#define NT 400000

// ---------------- scratch (device globals) --------------------------------------
__device__ float g_bondvec[NE * 3];
__device__ float g_dist[NE];
__device__ float g_rbf[NE * 9];
__device__ float g_cut3[NE];
__device__ float g_tbw[NT * 9];
__device__ int   g_endatom[NT];
__device__ float g_nodefeat[NN * 128];
__device__ float g_edgefeat[NE * 128];
__device__ float g_atoms[NN * 9];
__device__ float g_nb[NE * 9];
__device__ float g_nodepre[8 * NN * 128];   // slices: br*4 + chain*2 + side
__device__ float g_mean[128];
__device__ unsigned g_wbf16[6 * 6 * 128 * 64];  // [kbr][layer:{h0e,h1,h2,g0e,g1,g2}][128][64w]

struct Scales { float v[9]; };

__constant__ float c_roots[9] = {
    3.141592653589793f, 6.283185307179586f, 9.42477796076938f,
    4.493409457909064f, 7.725251836937707f, 10.904121659428899f,
    5.763459196894550f, 9.095011330476355f, 12.322940970566582f};

#define Y00F 0.28209479177387814f
#define Y10F 0.4886025119029199f
#define Y20F 0.31539156525252005f

__device__ __forceinline__ float siluf(float v) { return v / (1.f + expf(-v)); }
__device__ __forceinline__ float sigf(float v)  { return 1.f / (1.f + expf(-v)); }

__device__ __forceinline__ float jlf(int l, float x) {
    float s, c;
    sincosf(x, &s, &c);
    float inv = 1.f / x;
    if (l == 0) return s * inv;
    if (l == 1) return (s * inv - c) * inv;
    return (3.f * inv * inv - 1.f) * s * inv - 3.f * c * inv * inv;
}

// ---------------- mma / pack primitives -----------------------------------------
__device__ __forceinline__ unsigned f2tf(float x) {
    unsigned u;
    asm("cvt.rna.tf32.f32 %0, %1;" : "=r"(u) : "f"(x));
    return u;
}
__device__ __forceinline__ void mma_tf32(float* d, const unsigned* a, unsigned b0, unsigned b1) {
    asm volatile(
        "mma.sync.aligned.m16n8k8.row.col.f32.tf32.tf32.f32 "
        "{%0,%1,%2,%3}, {%4,%5,%6,%7}, {%8,%9}, {%0,%1,%2,%3};"
        : "+f"(d[0]), "+f"(d[1]), "+f"(d[2]), "+f"(d[3])
        : "r"(a[0]), "r"(a[1]), "r"(a[2]), "r"(a[3]), "r"(b0), "r"(b1));
}
__device__ __forceinline__ unsigned pack_bf16(float lo, float hi) {
    unsigned r;
    asm("cvt.rn.bf16x2.f32 %0, %1, %2;" : "=r"(r) : "f"(hi), "f"(lo));
    return r;
}
__device__ __forceinline__ float bf_lo(unsigned p) { return __uint_as_float(p << 16); }
__device__ __forceinline__ float bf_hi(unsigned p) { return __uint_as_float(p & 0xffff0000u); }
__device__ __forceinline__ void ldm_x4(unsigned& r0, unsigned& r1, unsigned& r2, unsigned& r3,
                                       unsigned addr) {
    asm volatile("ldmatrix.sync.aligned.m8n8.x4.shared.b16 {%0,%1,%2,%3}, [%4];"
                 : "=r"(r0), "=r"(r1), "=r"(r2), "=r"(r3) : "r"(addr));
}
__device__ __forceinline__ void ldm_x4_t(unsigned& r0, unsigned& r1, unsigned& r2, unsigned& r3,
                                         unsigned addr) {
    asm volatile("ldmatrix.sync.aligned.m8n8.x4.trans.shared.b16 {%0,%1,%2,%3}, [%4];"
                 : "=r"(r0), "=r"(r1), "=r"(r2), "=r"(r3) : "r"(addr));
}
__device__ __forceinline__ void mma_bf16(float* d, const unsigned* a, unsigned b0, unsigned b1) {
    asm volatile(
        "mma.sync.aligned.m16n8k16.row.col.f32.bf16.bf16.f32 "
        "{%0,%1,%2,%3}, {%4,%5,%6,%7}, {%8,%9}, {%0,%1,%2,%3};"
        : "+f"(d[0]), "+f"(d[1]), "+f"(d[2]), "+f"(d[3])
        : "r"(a[0]), "r"(a[1]), "r"(a[2]), "r"(a[3]), "r"(b0), "r"(b1));
}

// ---------------- weight pre-conversion (fp32 -> bf16x2) ------------------------
__global__ void k_convw(const float* __restrict__ W0, const float* __restrict__ W1,
                        const float* __restrict__ W2, const float* __restrict__ gW0,
                        const float* __restrict__ gW1, const float* __restrict__ gW2) {
    int idx = blockIdx.x * blockDim.x + threadIdx.x;
    if (idx >= 6 * 6 * 8192) return;
    int kbr = idx / 49152;
    int rem = idx - kbr * 49152;
    int l = rem / 8192;
    int pos = rem - l * 8192;
    int row = pos >> 6, cw = pos & 63;
    const float* src;
    if (l == 0)      src = W0  + (size_t)kbr * 384 * 128 + 256 * 128;
    else if (l == 1) src = W1  + (size_t)kbr * 128 * 128;
    else if (l == 2) src = W2  + (size_t)kbr * 128 * 128;
    else if (l == 3) src = gW0 + (size_t)kbr * 384 * 128 + 256 * 128;
    else if (l == 4) src = gW1 + (size_t)kbr * 128 * 128;
    else             src = gW2 + (size_t)kbr * 128 * 128;
    float2 v = *(const float2*)(src + row * 128 + cw * 2);
    g_wbf16[idx] = pack_bf16(v.x, v.y);
}

// ---------------- kernel 0: geom + nodeinit + zero mean -------------------------
__global__ void k_setup0(const float* __restrict__ pos, const int* __restrict__ src,
                         const int* __restrict__ dst, const int* __restrict__ node_type,
                         const float* __restrict__ emb, Scales sc) {
    int idx = blockIdx.x * blockDim.x + threadIdx.x;
    if (idx < NE) {
        int e = idx;
        int s = src[e], d = dst[e];
        float dx = pos[d * 3 + 0] - pos[s * 3 + 0];
        float dy = pos[d * 3 + 1] - pos[s * 3 + 1];
        float dz = pos[d * 3 + 2] - pos[s * 3 + 2];
        float dist = sqrtf(dx * dx + dy * dy + dz * dz + 1e-12f);
        g_bondvec[e * 3 + 0] = dx;
        g_bondvec[e * 3 + 1] = dy;
        g_bondvec[e * 3 + 2] = dz;
        g_dist[e] = dist;
#pragma unroll
        for (int l = 0; l < 3; l++)
#pragma unroll
            for (int n = 0; n < 3; n++)
                g_rbf[e * 9 + l * 3 + n] = jlf(l, dist * c_roots[l * 3 + n] * 0.2f) * sc.v[l * 3 + n];
        float xx = dist * 0.25f;
        float x2 = xx * xx, x3 = x2 * xx;
        g_cut3[e] = 1.f - 6.f * x3 * x2 + 15.f * x2 * x2 - 10.f * x3;
    } else if (idx < NE + NN * 128) {
        int i = idx - NE;
        int n = i >> 7, c = i & 127;
        g_nodefeat[i] = emb[node_type[n] * 128 + c];
    } else if (idx < NE + NN * 128 + 128) {
        g_mean[idx - NE - NN * 128] = 0.f;
    }
}

// ---------------- kernel 1: triplet + edgeemb -----------------------------------
__global__ void k_setup1(const int* __restrict__ t_src, const int* __restrict__ t_dst,
                         const int* __restrict__ dst,
                         const float* __restrict__ W, const float* __restrict__ b) {
    int idx = blockIdx.x * blockDim.x + threadIdx.x;
    if (idx < NT) {
        int t = idx;
        int es = t_src[t], ed = t_dst[t];
        float v1x = g_bondvec[es * 3 + 0], v1y = g_bondvec[es * 3 + 1], v1z = g_bondvec[es * 3 + 2];
        float v2x = g_bondvec[ed * 3 + 0], v2y = g_bondvec[ed * 3 + 1], v2z = g_bondvec[ed * 3 + 2];
        float cost = (v1x * v2x + v1y * v2y + v1z * v2z) / (g_dist[es] * g_dist[ed]);
        float shf0 = Y00F;
        float shf1 = Y10F * cost;
        float shf2 = Y20F * (3.f * cost * cost - 1.f);
        float tw = g_cut3[es] * g_cut3[ed];
#pragma unroll
        for (int n = 0; n < 3; n++) {
            g_tbw[t * 9 + n]     = g_rbf[ed * 9 + n] * shf0 * tw;
            g_tbw[t * 9 + 3 + n] = g_rbf[ed * 9 + 3 + n] * shf1 * tw;
            g_tbw[t * 9 + 6 + n] = g_rbf[ed * 9 + 6 + n] * shf2 * tw;
        }
        g_endatom[t] = dst[ed];
    } else if (idx < NT + NE * 128) {
        int i = idx - NT;
        int e = i >> 7, j = i & 127;
        float acc = b[j];
#pragma unroll
        for (int q = 0; q < 9; q++) acc = fmaf(g_rbf[e * 9 + q], W[q * 128 + j], acc);
        g_edgefeat[i] = siluf(acc);
    }
}

// ---------------- kernel 2: nodegemm(8 slices, tf32) + atoms + zero_nb ----------
#define NG_BLOCKS 320
#define AT_BLOCKS 176
#define ZB_BLOCKS 2110

__global__ void __launch_bounds__(256) k_block_setup(
    const float* __restrict__ W0, const float* __restrict__ gW0,
    const float* __restrict__ b0, const float* __restrict__ gb0,
    const float* __restrict__ taW, const float* __restrict__ tab, int k) {
    int blk = blockIdx.x;
    if (blk < NG_BLOCKS) {
        __shared__ unsigned sA[128 * 40];
        __shared__ unsigned sB[32 * 136];
        int slice = blk & 7, mt = blk >> 3;
        int br = slice >> 2, chain = (slice >> 1) & 1, side = slice & 1;
        const float* Wbase = (chain ? gW0 : W0) + (size_t)(k * 2 + br) * 384 * 128 + side * 128 * 128;
        const float* bias = side == 0 ? ((chain ? gb0 : b0) + (k * 2 + br) * 128) : nullptr;
        float* out = g_nodepre + (size_t)slice * NN * 128;
        const float* A = g_nodefeat;
        int bm = mt * 128;

        const int tid = threadIdx.x;
        const int lane = tid & 31, wid = tid >> 5;
        const int wm = (wid & 3) * 32, wn = (wid >> 2) * 64;
        float acc[2][8][4];
#pragma unroll
        for (int i = 0; i < 2; i++)
#pragma unroll
            for (int j = 0; j < 8; j++)
#pragma unroll
                for (int q = 0; q < 4; q++) acc[i][j][q] = 0.f;

        const int r0 = tid >> 3, c4 = tid & 7;
        const int bk0 = tid >> 5, bn4 = tid & 31;
        for (int kt = 0; kt < 4; kt++) {
#pragma unroll
            for (int i = 0; i < 4; i++) {
                int gm = bm + r0 + 32 * i;
                float4 v = make_float4(0.f, 0.f, 0.f, 0.f);
                if (gm < NN) v = *(const float4*)(A + (size_t)gm * 128 + kt * 32 + c4 * 4);
                uint4 u;
                u.x = f2tf(v.x); u.y = f2tf(v.y); u.z = f2tf(v.z); u.w = f2tf(v.w);
                *(uint4*)&sA[(r0 + 32 * i) * 40 + c4 * 4] = u;
            }
#pragma unroll
            for (int i = 0; i < 4; i++) {
                float4 v = *(const float4*)(Wbase + (size_t)(kt * 32 + bk0 + 8 * i) * 128 + bn4 * 4);
                uint4 u;
                u.x = f2tf(v.x); u.y = f2tf(v.y); u.z = f2tf(v.z); u.w = f2tf(v.w);
                *(uint4*)&sB[(bk0 + 8 * i) * 136 + bn4 * 4] = u;
            }
            __syncthreads();
#pragma unroll
            for (int ks = 0; ks < 4; ks++) {
                unsigned a[2][4];
                int arow = wm + (lane >> 2);
                int acol = ks * 8 + (lane & 3);
#pragma unroll
                for (int m2 = 0; m2 < 2; m2++) {
                    int rr = arow + m2 * 16;
                    a[m2][0] = sA[rr * 40 + acol];
                    a[m2][1] = sA[(rr + 8) * 40 + acol];
                    a[m2][2] = sA[rr * 40 + acol + 4];
                    a[m2][3] = sA[(rr + 8) * 40 + acol + 4];
                }
                int bro = (ks * 8 + (lane & 3)) * 136 + wn + (lane >> 2);
#pragma unroll
                for (int nt = 0; nt < 8; nt++) {
                    unsigned b0r = sB[bro + nt * 8];
                    unsigned b1r = sB[bro + 4 * 136 + nt * 8];
                    mma_tf32(acc[0][nt], a[0], b0r, b1r);
                    mma_tf32(acc[1][nt], a[1], b0r, b1r);
                }
            }
            __syncthreads();
        }
#pragma unroll
        for (int m2 = 0; m2 < 2; m2++) {
#pragma unroll
            for (int nt = 0; nt < 8; nt++) {
                int gn = wn + nt * 8 + 2 * (lane & 3);
                float bv0 = bias ? bias[gn] : 0.f;
                float bv1 = bias ? bias[gn + 1] : 0.f;
                int gm0 = bm + wm + m2 * 16 + (lane >> 2);
                if (gm0 < NN)
                    *(float2*)(out + (size_t)gm0 * 128 + gn) =
                        make_float2(acc[m2][nt][0] + bv0, acc[m2][nt][1] + bv1);
                int gm1 = gm0 + 8;
                if (gm1 < NN)
                    *(float2*)(out + (size_t)gm1 * 128 + gn) =
                        make_float2(acc[m2][nt][2] + bv0, acc[m2][nt][3] + bv1);
            }
        }
    } else if (blk < NG_BLOCKS + AT_BLOCKS) {
        int idx = (blk - NG_BLOCKS) * 256 + threadIdx.x;
        if (idx < NN * 9) {
            int n = idx / 9, j = idx % 9;
            float acc = tab[k * 9 + j];
            const float* nf = &g_nodefeat[n * 128];
            const float* W = taW + (size_t)k * 128 * 9;
#pragma unroll 8
            for (int i = 0; i < 128; i++) acc = fmaf(nf[i], W[i * 9 + j], acc);
            g_atoms[idx] = sigf(acc);
        }
    } else {
        int idx = (blk - NG_BLOCKS - AT_BLOCKS) * 256 + threadIdx.x;
        if (idx < NE * 9) g_nb[idx] = 0.f;
    }
}

// ---------------- tripacc --------------------------------------------------------
__global__ void k_tripacc(const int* __restrict__ t_src) {
    int t = blockIdx.x * blockDim.x + threadIdx.x;
    if (t >= NT) return;
    int es = t_src[t];
    int ea = g_endatom[t];
#pragma unroll
    for (int q = 0; q < 9; q++)
        atomicAdd(&g_nb[es * 9 + q], g_tbw[t * 9 + q] * g_atoms[ea * 9 + q]);
}

// ---------------- fused megakernel: BM=128, 512 threads, 1 CTA/SM ---------------
// smem bytes: sAct @0 (34816) | sAe @34816 (34816) | sB0 @69632 (17408) |
//             sB1 @87040 (17408) | sE f32 @104448 (69632) | swt @174080 (4608)
#define FUSED_SMEM 178688
#define FUSED_GRID ((NE + 127) / 128)
#define STR 136

__global__ void __launch_bounds__(512, 1) fused_block(
    const int* __restrict__ src, const int* __restrict__ dst,
    const float* __restrict__ Wbk, const float* __restrict__ Wgk,
    const unsigned* __restrict__ wbase,                 // bf16 weights, this k (2 branches)
    const float* __restrict__ b1k, const float* __restrict__ b2k,
    const float* __restrict__ gb1k, const float* __restrict__ gb2k,
    const float* __restrict__ wtk) {
    extern __shared__ char smem_raw[];
    unsigned* sActw = (unsigned*)(smem_raw);
    unsigned* sAew  = (unsigned*)(smem_raw + 34816);
    float*    sE    = (float*)(smem_raw + 104448);
    float*    swt   = (float*)(smem_raw + 174080);

    const unsigned act_u = (unsigned)__cvta_generic_to_shared(sActw);
    const unsigned ae_u  = (unsigned)__cvta_generic_to_shared(sAew);
    const unsigned b0_u  = (unsigned)__cvta_generic_to_shared(smem_raw + 69632);
    const unsigned b1_u  = (unsigned)__cvta_generic_to_shared(smem_raw + 87040);

    const int tid = threadIdx.x;
    const int lane = tid & 31, wid = tid >> 5;
    const int wm = (wid & 7) * 16, wn = (wid >> 3) * 64;
    const int bm = blockIdx.x * 128;

    const int rr0 = wm + (lane >> 2);
    const int e0 = bm + rr0, e1 = e0 + 8;
    const bool v0 = e0 < NE, v1 = e1 < NE;
    const int s0 = v0 ? src[e0] : 0, d0 = v0 ? dst[e0] : 0;
    const int s1 = v1 ? src[e1] : 0, d1 = v1 ? dst[e1] : 0;

    // ---- stage A: three-body edge update into sE -------------------------------
    {
        float* sWb = (float*)sActw;
        float* sWg = (float*)sAew;
        for (int i = tid; i < 9 * 128; i += 512) { sWb[i] = Wbk[i]; sWg[i] = Wgk[i]; }
        __syncthreads();
        for (int i = tid; i < 128 * 128; i += 512) {
            int row = i >> 7, col = i & 127;
            int e = bm + row;
            float val = 0.f;
            if (e < NE) {
                float s1v = 0.f, s2v = 0.f;
#pragma unroll
                for (int q = 0; q < 9; q++) {
                    float nv = g_nb[e * 9 + q];
                    s1v = fmaf(nv, sWb[q * 128 + col], s1v);
                    s2v = fmaf(nv, sWg[q * 128 + col], s2v);
                }
                val = g_edgefeat[(size_t)e * 128 + col] + siluf(s1v) * sigf(s2v);
            }
            sE[row * STR + col] = val;
        }
        __syncthreads();
    }

    float acc[8][4];
    unsigned hpk[8][2];   // silu(h2) packed bf16x2

    auto zero_acc = [&] {
#pragma unroll
        for (int j = 0; j < 8; j++)
#pragma unroll
            for (int q = 0; q < 4; q++) acc[j][q] = 0.f;
    };
    // async-copy one 64x128 bf16 weight slab (row stride 272B in smem)
    auto cp_slab = [&](const unsigned* Wb, int slab, unsigned bufu) {
#pragma unroll
        for (int i = 0; i < 2; i++) {
            int c = tid + 512 * i;
            int row = c >> 4, c4 = c & 15;
            unsigned dstb = bufu + (unsigned)(row * 272 + c4 * 16);
            const unsigned* srcp = Wb + (slab * 64 + row) * 64 + c4 * 4;
            asm volatile("cp.async.cg.shared.global [%0], [%1], 16;"
                         :: "r"(dstb), "l"(srcp) : "memory");
        }
        asm volatile("cp.async.commit_group;" ::: "memory");
    };
    auto compute_tile = [&](unsigned abase, unsigned bbase, int kbase) {
        unsigned a[4];
        {
            int arow = wm + (lane & 7) + ((lane >> 3) & 1) * 8;
            int acol = kbase + (lane >> 4) * 8;
            ldm_x4(a[0], a[1], a[2], a[3], abase + (unsigned)(arow * STR + acol) * 2);
        }
        int krow = (kbase & 63) + (lane & 15);
        int cofs = (lane >> 4) * 8;
#pragma unroll
        for (int j = 0; j < 4; j++) {
            unsigned b[4];
            int n0 = wn + 16 * j;
            ldm_x4_t(b[0], b[1], b[2], b[3], bbase + (unsigned)(krow * STR + n0 + cofs) * 2);
            mma_bf16(acc[2 * j], a, b[0], b[1]);
            mma_bf16(acc[2 * j + 1], a, b[2], b[3]);
        }
    };
    auto gemm_layer = [&](unsigned abase, const unsigned* Wb) {
        zero_acc();
        cp_slab(Wb, 0, b0_u);
        asm volatile("cp.async.wait_group 0;" ::: "memory");
        __syncthreads();
        cp_slab(Wb, 1, b1_u);
#pragma unroll
        for (int ks = 0; ks < 4; ks++) compute_tile(abase, b0_u, ks * 16);
        asm volatile("cp.async.wait_group 0;" ::: "memory");
        __syncthreads();
#pragma unroll
        for (int ks = 0; ks < 4; ks++) compute_tile(abase, b1_u, 64 + ks * 16);
        __syncthreads();
    };
    auto conv_sE = [&] {
        for (int i = tid; i < 128 * 64; i += 512) {
            int row = i >> 6, cp = i & 63;
            sAew[row * 68 + cp] = pack_bf16(sE[row * STR + 2 * cp], sE[row * STR + 2 * cp + 1]);
        }
    };

    // one gated-MLP chain; leaves final raw L2 pre-activation in acc.
    auto run_chain = [&](const unsigned* wch, const float* NS, const float* ND,
                         const float* b1v) {
        gemm_layer(ae_u, wch);                      // L0 (A = edge tile)
#pragma unroll
        for (int nt = 0; nt < 8; nt++) {
            int gn = wn + nt * 8 + 2 * (lane & 3);
            float2 ns0 = v0 ? *(const float2*)(NS + (size_t)s0 * 128 + gn) : make_float2(0, 0);
            float2 nd0 = v0 ? *(const float2*)(ND + (size_t)d0 * 128 + gn) : make_float2(0, 0);
            float2 ns1 = v1 ? *(const float2*)(NS + (size_t)s1 * 128 + gn) : make_float2(0, 0);
            float2 nd1 = v1 ? *(const float2*)(ND + (size_t)d1 * 128 + gn) : make_float2(0, 0);
            sActw[rr0 * 68 + (gn >> 1)] =
                pack_bf16(siluf(acc[nt][0] + ns0.x + nd0.x), siluf(acc[nt][1] + ns0.y + nd0.y));
            sActw[(rr0 + 8) * 68 + (gn >> 1)] =
                pack_bf16(siluf(acc[nt][2] + ns1.x + nd1.x), siluf(acc[nt][3] + ns1.y + nd1.y));
        }
        gemm_layer(act_u, wch + 8192);              // L1
#pragma unroll
        for (int nt = 0; nt < 8; nt++) {
            int gn = wn + nt * 8 + 2 * (lane & 3);
            float bv0 = b1v[gn], bv1 = b1v[gn + 1];
            sActw[rr0 * 68 + (gn >> 1)] =
                pack_bf16(siluf(acc[nt][0] + bv0), siluf(acc[nt][1] + bv1));
            sActw[(rr0 + 8) * 68 + (gn >> 1)] =
                pack_bf16(siluf(acc[nt][2] + bv0), siluf(acc[nt][3] + bv1));
        }
        gemm_layer(act_u, wch + 16384);             // L2 -> raw acc
    };

    for (int br = 0; br < 2; br++) {
        const unsigned* wbr = wbase + (size_t)br * 49152;
        const float* bh1 = b1k + br * 128;
        const float* bg1 = gb1k + br * 128;
        const float* bh2 = b2k + br * 128;
        const float* bg2 = gb2k + br * 128;
        const float* NSh = g_nodepre + (size_t)(br * 4 + 0) * NN * 128;
        const float* NDh = g_nodepre + (size_t)(br * 4 + 1) * NN * 128;
        const float* NSg = g_nodepre + (size_t)(br * 4 + 2) * NN * 128;
        const float* NDg = g_nodepre + (size_t)(br * 4 + 3) * NN * 128;

        conv_sE();
        for (int i = tid; i < 9 * 128; i += 512) swt[i] = wtk[br * 9 * 128 + i];
        // ordering provided by first gemm_layer's internal barrier

        // h chain -> pack silu(h2) to bf16x2
        run_chain(wbr, NSh, NDh, bh1);
#pragma unroll
        for (int nt = 0; nt < 8; nt++) {
            int gn = wn + nt * 8 + 2 * (lane & 3);
            float bv0 = bh2[gn], bv1 = bh2[gn + 1];
            hpk[nt][0] = pack_bf16(siluf(acc[nt][0] + bv0), siluf(acc[nt][1] + bv1));
            hpk[nt][1] = pack_bf16(siluf(acc[nt][2] + bv0), siluf(acc[nt][3] + bv1));
        }
        // g chain (raw L2 in acc)
        run_chain(wbr + 24576, NSg, NDg, bg1);

        // ---- epilogue ----
        float rb0[9], rb1[9];
#pragma unroll
        for (int q = 0; q < 9; q++) {
            rb0[q] = v0 ? g_rbf[e0 * 9 + q] : 0.f;
            rb1[q] = v1 ? g_rbf[e1 * 9 + q] : 0.f;
        }
#pragma unroll
        for (int nt = 0; nt < 8; nt++) {
            int gn = wn + nt * 8 + 2 * (lane & 3);
            float w00 = 0.f, w01 = 0.f, w10 = 0.f, w11 = 0.f;
#pragma unroll
            for (int q = 0; q < 9; q++) {
                float wc0 = swt[q * 128 + gn], wc1 = swt[q * 128 + gn + 1];
                w00 = fmaf(rb0[q], wc0, w00);
                w01 = fmaf(rb0[q], wc1, w01);
                w10 = fmaf(rb1[q], wc0, w10);
                w11 = fmaf(rb1[q], wc1, w11);
            }
            float gb0v = bg2[gn], gb1v = bg2[gn + 1];
            float val0 = bf_lo(hpk[nt][0]) * sigf(acc[nt][0] + gb0v) * w00;
            float val1 = bf_hi(hpk[nt][0]) * sigf(acc[nt][1] + gb1v) * w01;
            float val2 = bf_lo(hpk[nt][1]) * sigf(acc[nt][2] + gb0v) * w10;
            float val3 = bf_hi(hpk[nt][1]) * sigf(acc[nt][3] + gb1v) * w11;
            if (br == 0) {
                if (v0) {
                    float n0v = sE[rr0 * STR + gn] + val0;
                    float n1v = sE[rr0 * STR + gn + 1] + val1;
                    sE[rr0 * STR + gn] = n0v;
                    sE[rr0 * STR + gn + 1] = n1v;
                    *(float2*)(g_edgefeat + (size_t)e0 * 128 + gn) = make_float2(n0v, n1v);
                }
                if (v1) {
                    float n2v = sE[(rr0 + 8) * STR + gn] + val2;
                    float n3v = sE[(rr0 + 8) * STR + gn + 1] + val3;
                    sE[(rr0 + 8) * STR + gn] = n2v;
                    sE[(rr0 + 8) * STR + gn + 1] = n3v;
                    *(float2*)(g_edgefeat + (size_t)e1 * 128 + gn) = make_float2(n2v, n3v);
                }
            } else {
                if (v0) {
                    atomicAdd(&g_nodefeat[(size_t)d0 * 128 + gn], val0);
                    atomicAdd(&g_nodefeat[(size_t)d0 * 128 + gn + 1], val1);
                }
                if (v1) {
                    atomicAdd(&g_nodefeat[(size_t)d1 * 128 + gn], val2);
                    atomicAdd(&g_nodefeat[(size_t)d1 * 128 + gn + 1], val3);
                }
            }
        }
        __syncthreads();
    }
}

// ---------------- readout -------------------------------------------------------
__global__ void k_mean() {
    int j = threadIdx.x;
    int b = blockIdx.x;
    float s = 0.f;
    for (int n = b * 125; n < b * 125 + 125; n++) s += g_nodefeat[n * 128 + j];
    atomicAdd(&g_mean[j], s);
}

__global__ void k_final(const float* __restrict__ fW0, const float* __restrict__ fb0,
                        const float* __restrict__ fW1, const float* __restrict__ fb1,
                        const float* __restrict__ fW2, const float* __restrict__ fb2,
                        float* __restrict__ out) {
    __shared__ float v[128], h0[128], h1[128], red[128];
    int j = threadIdx.x;
    v[j] = g_mean[j] / (float)NN;
    __syncthreads();
    float a = fb0[j];
    for (int i = 0; i < 128; i++) a = fmaf(v[i], fW0[i * 128 + j], a);
    h0[j] = siluf(a);
    __syncthreads();
    a = fb1[j];
    for (int i = 0; i < 128; i++) a = fmaf(h0[i], fW1[i * 128 + j], a);
    h1[j] = siluf(a);
    __syncthreads();
    red[j] = h1[j] * fW2[j];
    __syncthreads();
    for (int st = 64; st > 0; st >>= 1) {
        if (j < st) red[j] += red[j + st];
        __syncthreads();
    }
    if (j == 0) out[0] = red[0] + fb2[0];
}

// ---------------- host ----------------------------------------------------------
static double h_jl(int l, double x) {
    double s = sin(x), c = cos(x);
    if (l == 1) return s / (x * x) - c / x;
    if (l == 2) return (3.0 / (x * x * x) - 1.0 / x) * s - 3.0 * c / (x * x);
    return (15.0 / (x * x * x * x) - 6.0 / (x * x)) * s - (15.0 / (x * x * x) - 1.0 / x) * c;
}

extern "C" void kernel_launch(void* const* d_in, const int* in_sizes, int n_in,
                              void* d_out, int out_size) {
    const float* pos  = (const float*)d_in[0];
    const int* node_type = (const int*)d_in[1];
    const int* src  = (const int*)d_in[2];
    const int* dst  = (const int*)d_in[3];
    const int* t_src = (const int*)d_in[4];
    const int* t_dst = (const int*)d_in[5];
    const float* emb  = (const float*)d_in[6];
    const float* eW   = (const float*)d_in[7];
    const float* eb   = (const float*)d_in[8];
    const float* taW  = (const float*)d_in[9];
    const float* tab  = (const float*)d_in[10];
    const float* tbW  = (const float*)d_in[11];
    const float* tbWg = (const float*)d_in[12];
    const float* W0 = (const float*)d_in[13];  const float* b0 = (const float*)d_in[14];
    const float* W1 = (const float*)d_in[15];  const float* b1 = (const float*)d_in[16];
    const float* W2 = (const float*)d_in[17];  const float* b2 = (const float*)d_in[18];
    const float* gW0 = (const float*)d_in[19]; const float* gb0 = (const float*)d_in[20];
    const float* gW1 = (const float*)d_in[21]; const float* gb1 = (const float*)d_in[22];
    const float* gW2 = (const float*)d_in[23]; const float* gb2 = (const float*)d_in[24];
    const float* wt = (const float*)d_in[25];
    const float* fW0 = (const float*)d_in[26]; const float* fb0 = (const float*)d_in[27];
    const float* fW1 = (const float*)d_in[28]; const float* fb1 = (const float*)d_in[29];
    const float* fW2 = (const float*)d_in[30]; const float* fb2 = (const float*)d_in[31];
    float* out = (float*)d_out;

    Scales sc;
    {
        const double roots[9] = {
            3.141592653589793, 6.283185307179586, 9.42477796076938,
            4.493409457909064, 7.725251836937707, 10.904121659428899,
            5.763459196894550, 9.095011330476355, 12.322940970566582};
        double fac = sqrt(2.0 / 125.0);
        for (int l = 0; l < 3; l++)
            for (int n = 0; n < 3; n++)
                sc.v[l * 3 + n] = (float)(fac / fabs(h_jl(l + 1, roots[l * 3 + n])));
    }

    unsigned* pwb;
    cudaGetSymbolAddress((void**)&pwb, g_wbf16);

    cudaFuncSetAttribute(fused_block, cudaFuncAttributeMaxDynamicSharedMemorySize, FUSED_SMEM);

    k_convw<<<(6 * 6 * 8192 + 255) / 256, 256>>>(W0, W1, W2, gW0, gW1, gW2);
    int n0 = NE + NN * 128 + 128;
    k_setup0<<<(n0 + 255) / 256, 256>>>(pos, src, dst, node_type, emb, sc);
    int n1 = NT + NE * 128;
    k_setup1<<<(n1 + 255) / 256, 256>>>(t_src, t_dst, dst, eW, eb);

    for (int k = 0; k < 3; k++) {
        k_block_setup<<<NG_BLOCKS + AT_BLOCKS + ZB_BLOCKS, 256>>>(W0, gW0, b0, gb0, taW, tab, k);
        k_tripacc<<<(NT + 255) / 256, 256>>>(t_src);
        fused_block<<<FUSED_GRID, 512, FUSED_SMEM>>>(
            src, dst, tbW + k * 9 * 128, tbWg + k * 9 * 128,
            pwb + (size_t)k * 2 * 49152,
            b1 + k * 2 * 128, b2 + k * 2 * 128,
            gb1 + k * 2 * 128, gb2 + k * 2 * 128,
            wt + k * 2 * 9 * 128);
    }
    k_mean<<<40, 128>>>();
    k_final<<<1, 128>>>(fW0, fb0, fW1, fb1, fW2, fb2, out);
}

// round 14
// speedup vs baseline: 1.0455x; 1.0440x over previous
#include <cuda_runtime.h>
#include <math.h>

#define NN 5000
#define NE 60000
#define NT 400000

// ---------------- scratch (device globals) --------------------------------------
__device__ float g_bondvec[NE * 3];
__device__ float g_dist[NE];
__device__ float g_rbf[NE * 9];
__device__ float g_cut3[NE];
__device__ float g_tbw[NT * 9];
__device__ int   g_endatom[NT];
__device__ float g_nodefeat[NN * 128];
__device__ float g_edgefeat[NE * 128];
__device__ float g_atoms[NN * 9];
__device__ float g_nb[NE * 9];
__device__ float g_nodepre[8 * NN * 128];   // slices: br*4 + chain*2 + side
__device__ float g_mean[128];
__device__ unsigned g_wbf16[6 * 6 * 128 * 64];  // [kbr][layer:{h0e,h1,h2,g0e,g1,g2}][128][64w]

struct Scales { float v[9]; };

__constant__ float c_roots[9] = {
    3.141592653589793f, 6.283185307179586f, 9.42477796076938f,
    4.493409457909064f, 7.725251836937707f, 10.904121659428899f,
    5.763459196894550f, 9.095011330476355f, 12.322940970566582f};

#define Y00F 0.28209479177387814f
#define Y10F 0.4886025119029199f
#define Y20F 0.31539156525252005f

__device__ __forceinline__ float siluf(float v) { return v / (1.f + expf(-v)); }
__device__ __forceinline__ float sigf(float v)  { return 1.f / (1.f + expf(-v)); }

__device__ __forceinline__ float jlf(int l, float x) {
    float s, c;
    sincosf(x, &s, &c);
    float inv = 1.f / x;
    if (l == 0) return s * inv;
    if (l == 1) return (s * inv - c) * inv;
    return (3.f * inv * inv - 1.f) * s * inv - 3.f * c * inv * inv;
}

// ---------------- mma / pack primitives -----------------------------------------
__device__ __forceinline__ unsigned f2tf(float x) {
    unsigned u;
    asm("cvt.rna.tf32.f32 %0, %1;" : "=r"(u) : "f"(x));
    return u;
}
__device__ __forceinline__ void mma_tf32(float* d, const unsigned* a, unsigned b0, unsigned b1) {
    asm volatile(
        "mma.sync.aligned.m16n8k8.row.col.f32.tf32.tf32.f32 "
        "{%0,%1,%2,%3}, {%4,%5,%6,%7}, {%8,%9}, {%0,%1,%2,%3};"
        : "+f"(d[0]), "+f"(d[1]), "+f"(d[2]), "+f"(d[3])
        : "r"(a[0]), "r"(a[1]), "r"(a[2]), "r"(a[3]), "r"(b0), "r"(b1));
}
__device__ __forceinline__ unsigned pack_bf16(float lo, float hi) {
    unsigned r;
    asm("cvt.rn.bf16x2.f32 %0, %1, %2;" : "=r"(r) : "f"(hi), "f"(lo));
    return r;
}
__device__ __forceinline__ float bf_lo(unsigned p) { return __uint_as_float(p << 16); }
__device__ __forceinline__ float bf_hi(unsigned p) { return __uint_as_float(p & 0xffff0000u); }
__device__ __forceinline__ void ldm_x4(unsigned& r0, unsigned& r1, unsigned& r2, unsigned& r3,
                                       unsigned addr) {
    asm volatile("ldmatrix.sync.aligned.m8n8.x4.shared.b16 {%0,%1,%2,%3}, [%4];"
                 : "=r"(r0), "=r"(r1), "=r"(r2), "=r"(r3) : "r"(addr));
}
__device__ __forceinline__ void ldm_x4_t(unsigned& r0, unsigned& r1, unsigned& r2, unsigned& r3,
                                         unsigned addr) {
    asm volatile("ldmatrix.sync.aligned.m8n8.x4.trans.shared.b16 {%0,%1,%2,%3}, [%4];"
                 : "=r"(r0), "=r"(r1), "=r"(r2), "=r"(r3) : "r"(addr));
}
__device__ __forceinline__ void mma_bf16(float* d, const unsigned* a, unsigned b0, unsigned b1) {
    asm volatile(
        "mma.sync.aligned.m16n8k16.row.col.f32.bf16.bf16.f32 "
        "{%0,%1,%2,%3}, {%4,%5,%6,%7}, {%8,%9}, {%0,%1,%2,%3};"
        : "+f"(d[0]), "+f"(d[1]), "+f"(d[2]), "+f"(d[3])
        : "r"(a[0]), "r"(a[1]), "r"(a[2]), "r"(a[3]), "r"(b0), "r"(b1));
}

// ---------------- kernel 0: geom + nodeinit + zero mean + weight conv -----------
#define CONVW_N (6 * 6 * 8192)
__global__ void k_setup0(const float* __restrict__ pos, const int* __restrict__ src,
                         const int* __restrict__ dst, const int* __restrict__ node_type,
                         const float* __restrict__ emb, Scales sc,
                         const float* __restrict__ W0, const float* __restrict__ W1,
                         const float* __restrict__ W2, const float* __restrict__ gW0,
                         const float* __restrict__ gW1, const float* __restrict__ gW2) {
    int idx = blockIdx.x * blockDim.x + threadIdx.x;
    if (idx < NE) {
        int e = idx;
        int s = src[e], d = dst[e];
        float dx = pos[d * 3 + 0] - pos[s * 3 + 0];
        float dy = pos[d * 3 + 1] - pos[s * 3 + 1];
        float dz = pos[d * 3 + 2] - pos[s * 3 + 2];
        float dist = sqrtf(dx * dx + dy * dy + dz * dz + 1e-12f);
        g_bondvec[e * 3 + 0] = dx;
        g_bondvec[e * 3 + 1] = dy;
        g_bondvec[e * 3 + 2] = dz;
        g_dist[e] = dist;
#pragma unroll
        for (int l = 0; l < 3; l++)
#pragma unroll
            for (int n = 0; n < 3; n++)
                g_rbf[e * 9 + l * 3 + n] = jlf(l, dist * c_roots[l * 3 + n] * 0.2f) * sc.v[l * 3 + n];
        float xx = dist * 0.25f;
        float x2 = xx * xx, x3 = x2 * xx;
        g_cut3[e] = 1.f - 6.f * x3 * x2 + 15.f * x2 * x2 - 10.f * x3;
    } else if (idx < NE + NN * 128) {
        int i = idx - NE;
        int n = i >> 7, c = i & 127;
        g_nodefeat[i] = emb[node_type[n] * 128 + c];
    } else if (idx < NE + NN * 128 + 128) {
        g_mean[idx - NE - NN * 128] = 0.f;
    } else if (idx < NE + NN * 128 + 128 + CONVW_N) {
        int w = idx - (NE + NN * 128 + 128);
        int kbr = w / 49152;
        int rem = w - kbr * 49152;
        int l = rem / 8192;
        int pos_ = rem - l * 8192;
        int row = pos_ >> 6, cw = pos_ & 63;
        const float* srcw;
        if (l == 0)      srcw = W0  + (size_t)kbr * 384 * 128 + 256 * 128;
        else if (l == 1) srcw = W1  + (size_t)kbr * 128 * 128;
        else if (l == 2) srcw = W2  + (size_t)kbr * 128 * 128;
        else if (l == 3) srcw = gW0 + (size_t)kbr * 384 * 128 + 256 * 128;
        else if (l == 4) srcw = gW1 + (size_t)kbr * 128 * 128;
        else             srcw = gW2 + (size_t)kbr * 128 * 128;
        float2 v = *(const float2*)(srcw + row * 128 + cw * 2);
        g_wbf16[w] = pack_bf16(v.x, v.y);
    }
}

// ---------------- kernel 1: triplet (+fused k=0 scatter) + edgeemb --------------
// g_nb must be zeroed and g_atoms (k=0) computed BEFORE this kernel (k_block_setup).
__global__ void k_setup1(const int* __restrict__ t_src, const int* __restrict__ t_dst,
                         const int* __restrict__ dst,
                         const float* __restrict__ W, const float* __restrict__ b) {
    int idx = blockIdx.x * blockDim.x + threadIdx.x;
    if (idx < NT) {
        int t = idx;
        int es = t_src[t], ed = t_dst[t];
        float v1x = g_bondvec[es * 3 + 0], v1y = g_bondvec[es * 3 + 1], v1z = g_bondvec[es * 3 + 2];
        float v2x = g_bondvec[ed * 3 + 0], v2y = g_bondvec[ed * 3 + 1], v2z = g_bondvec[ed * 3 + 2];
        float cost = (v1x * v2x + v1y * v2y + v1z * v2z) / (g_dist[es] * g_dist[ed]);
        float shf[3];
        shf[0] = Y00F;
        shf[1] = Y10F * cost;
        shf[2] = Y20F * (3.f * cost * cost - 1.f);
        float tw = g_cut3[es] * g_cut3[ed];
        int ea = dst[ed];
        g_endatom[t] = ea;
        float tb[9];
#pragma unroll
        for (int l = 0; l < 3; l++)
#pragma unroll
            for (int n = 0; n < 3; n++)
                tb[l * 3 + n] = g_rbf[ed * 9 + l * 3 + n] * shf[l] * tw;
#pragma unroll
        for (int q = 0; q < 9; q++) {
            g_tbw[t * 9 + q] = tb[q];
            atomicAdd(&g_nb[es * 9 + q], tb[q] * g_atoms[ea * 9 + q]);  // k=0 tripacc fused
        }
    } else if (idx < NT + NE * 128) {
        int i = idx - NT;
        int e = i >> 7, j = i & 127;
        float acc = b[j];
#pragma unroll
        for (int q = 0; q < 9; q++) acc = fmaf(g_rbf[e * 9 + q], W[q * 128 + j], acc);
        g_edgefeat[i] = siluf(acc);
    }
}

// ---------------- kernel 2: nodegemm(8 slices, tf32) + atoms + zero_nb ----------
#define NG_BLOCKS 320
#define AT_BLOCKS 176
#define ZB_BLOCKS 2110

__global__ void __launch_bounds__(256) k_block_setup(
    const float* __restrict__ W0, const float* __restrict__ gW0,
    const float* __restrict__ b0, const float* __restrict__ gb0,
    const float* __restrict__ taW, const float* __restrict__ tab, int k) {
    int blk = blockIdx.x;
    if (blk < NG_BLOCKS) {
        __shared__ unsigned sA[128 * 40];
        __shared__ unsigned sB[32 * 136];
        int slice = blk & 7, mt = blk >> 3;
        int br = slice >> 2, chain = (slice >> 1) & 1, side = slice & 1;
        const float* Wbase = (chain ? gW0 : W0) + (size_t)(k * 2 + br) * 384 * 128 + side * 128 * 128;
        const float* bias = side == 0 ? ((chain ? gb0 : b0) + (k * 2 + br) * 128) : nullptr;
        float* out = g_nodepre + (size_t)slice * NN * 128;
        const float* A = g_nodefeat;
        int bm = mt * 128;

        const int tid = threadIdx.x;
        const int lane = tid & 31, wid = tid >> 5;
        const int wm = (wid & 3) * 32, wn = (wid >> 2) * 64;
        float acc[2][8][4];
#pragma unroll
        for (int i = 0; i < 2; i++)
#pragma unroll
            for (int j = 0; j < 8; j++)
#pragma unroll
                for (int q = 0; q < 4; q++) acc[i][j][q] = 0.f;

        const int r0 = tid >> 3, c4 = tid & 7;
        const int bk0 = tid >> 5, bn4 = tid & 31;
        for (int kt = 0; kt < 4; kt++) {
#pragma unroll
            for (int i = 0; i < 4; i++) {
                int gm = bm + r0 + 32 * i;
                float4 v = make_float4(0.f, 0.f, 0.f, 0.f);
                if (gm < NN) v = *(const float4*)(A + (size_t)gm * 128 + kt * 32 + c4 * 4);
                uint4 u;
                u.x = f2tf(v.x); u.y = f2tf(v.y); u.z = f2tf(v.z); u.w = f2tf(v.w);
                *(uint4*)&sA[(r0 + 32 * i) * 40 + c4 * 4] = u;
            }
#pragma unroll
            for (int i = 0; i < 4; i++) {
                float4 v = *(const float4*)(Wbase + (size_t)(kt * 32 + bk0 + 8 * i) * 128 + bn4 * 4);
                uint4 u;
                u.x = f2tf(v.x); u.y = f2tf(v.y); u.z = f2tf(v.z); u.w = f2tf(v.w);
                *(uint4*)&sB[(bk0 + 8 * i) * 136 + bn4 * 4] = u;
            }
            __syncthreads();
#pragma unroll
            for (int ks = 0; ks < 4; ks++) {
                unsigned a[2][4];
                int arow = wm + (lane >> 2);
                int acol = ks * 8 + (lane & 3);
#pragma unroll
                for (int m2 = 0; m2 < 2; m2++) {
                    int rr = arow + m2 * 16;
                    a[m2][0] = sA[rr * 40 + acol];
                    a[m2][1] = sA[(rr + 8) * 40 + acol];
                    a[m2][2] = sA[rr * 40 + acol + 4];
                    a[m2][3] = sA[(rr + 8) * 40 + acol + 4];
                }
                int bro = (ks * 8 + (lane & 3)) * 136 + wn + (lane >> 2);
#pragma unroll
                for (int nt = 0; nt < 8; nt++) {
                    unsigned b0r = sB[bro + nt * 8];
                    unsigned b1r = sB[bro + 4 * 136 + nt * 8];
                    mma_tf32(acc[0][nt], a[0], b0r, b1r);
                    mma_tf32(acc[1][nt], a[1], b0r, b1r);
                }
            }
            __syncthreads();
        }
#pragma unroll
        for (int m2 = 0; m2 < 2; m2++) {
#pragma unroll
            for (int nt = 0; nt < 8; nt++) {
                int gn = wn + nt * 8 + 2 * (lane & 3);
                float bv0 = bias ? bias[gn] : 0.f;
                float bv1 = bias ? bias[gn + 1] : 0.f;
                int gm0 = bm + wm + m2 * 16 + (lane >> 2);
                if (gm0 < NN)
                    *(float2*)(out + (size_t)gm0 * 128 + gn) =
                        make_float2(acc[m2][nt][0] + bv0, acc[m2][nt][1] + bv1);
                int gm1 = gm0 + 8;
                if (gm1 < NN)
                    *(float2*)(out + (size_t)gm1 * 128 + gn) =
                        make_float2(acc[m2][nt][2] + bv0, acc[m2][nt][3] + bv1);
            }
        }
    } else if (blk < NG_BLOCKS + AT_BLOCKS) {
        int idx = (blk - NG_BLOCKS) * 256 + threadIdx.x;
        if (idx < NN * 9) {
            int n = idx / 9, j = idx % 9;
            float acc = tab[k * 9 + j];
            const float* nf = &g_nodefeat[n * 128];
            const float* W = taW + (size_t)k * 128 * 9;
#pragma unroll 8
            for (int i = 0; i < 128; i++) acc = fmaf(nf[i], W[i * 9 + j], acc);
            g_atoms[idx] = sigf(acc);
        }
    } else {
        int idx = (blk - NG_BLOCKS - AT_BLOCKS) * 256 + threadIdx.x;
        if (idx < NE * 9) g_nb[idx] = 0.f;
    }
}

// ---------------- tripacc (k=1,2 only; k=0 fused into setup1) -------------------
__global__ void k_tripacc(const int* __restrict__ t_src) {
    int t = blockIdx.x * blockDim.x + threadIdx.x;
    if (t >= NT) return;
    int es = t_src[t];
    int ea = g_endatom[t];
#pragma unroll
    for (int q = 0; q < 9; q++)
        atomicAdd(&g_nb[es * 9 + q], g_tbw[t * 9 + q] * g_atoms[ea * 9 + q]);
}

// ---------------- fused megakernel: tb-update + both branches (BM=64) -----------
// smem bytes: sAct @0 (17408) | sAe @17408 (17408) | sB0 @34816 (17408) |
//             sB1 @52224 (17408) | sE f32 @69632 (34816) | swt @104448 (4608)
#define FUSED_SMEM 109056
#define FUSED_GRID ((NE + 63) / 64)
#define STR 136

__global__ void __launch_bounds__(256, 2) fused_block(
    const int* __restrict__ src, const int* __restrict__ dst,
    const float* __restrict__ Wbk, const float* __restrict__ Wgk,
    const unsigned* __restrict__ wbase,                 // bf16 weights, this k (2 branches)
    const float* __restrict__ b1k, const float* __restrict__ b2k,
    const float* __restrict__ gb1k, const float* __restrict__ gb2k,
    const float* __restrict__ wtk) {
    extern __shared__ char smem_raw[];
    unsigned* sActw = (unsigned*)(smem_raw);
    unsigned* sAew  = (unsigned*)(smem_raw + 17408);
    float*    sE    = (float*)(smem_raw + 69632);
    float*    swt   = (float*)(smem_raw + 104448);

    const unsigned act_u = (unsigned)__cvta_generic_to_shared(sActw);
    const unsigned ae_u  = (unsigned)__cvta_generic_to_shared(sAew);
    const unsigned b0_u  = (unsigned)__cvta_generic_to_shared(smem_raw + 34816);
    const unsigned b1_u  = (unsigned)__cvta_generic_to_shared(smem_raw + 52224);

    const int tid = threadIdx.x;
    const int lane = tid & 31, wid = tid >> 5;
    const int wm = (wid & 3) * 16, wn = (wid >> 2) * 64;
    const int bm = blockIdx.x * 64;

    const int rr0 = wm + (lane >> 2);
    const int e0 = bm + rr0, e1 = e0 + 8;
    const bool v0 = e0 < NE, v1 = e1 < NE;
    const int s0 = v0 ? src[e0] : 0, d0 = v0 ? dst[e0] : 0;
    const int s1 = v1 ? src[e1] : 0, d1 = v1 ? dst[e1] : 0;

    // ---- stage A: three-body edge update into sE -------------------------------
    {
        float* sWb = (float*)sActw;
        float* sWg = (float*)sAew;
        for (int i = tid; i < 9 * 128; i += 256) { sWb[i] = Wbk[i]; sWg[i] = Wgk[i]; }
        __syncthreads();
        for (int i = tid; i < 64 * 128; i += 256) {
            int row = i >> 7, col = i & 127;
            int e = bm + row;
            float val = 0.f;
            if (e < NE) {
                float s1v = 0.f, s2v = 0.f;
#pragma unroll
                for (int q = 0; q < 9; q++) {
                    float nv = g_nb[e * 9 + q];
                    s1v = fmaf(nv, sWb[q * 128 + col], s1v);
                    s2v = fmaf(nv, sWg[q * 128 + col], s2v);
                }
                val = g_edgefeat[(size_t)e * 128 + col] + siluf(s1v) * sigf(s2v);
            }
            sE[row * STR + col] = val;
        }
        __syncthreads();
    }

    float acc[8][4];
    unsigned hpk[8][2];   // silu(h2) packed bf16x2

    auto zero_acc = [&] {
#pragma unroll
        for (int j = 0; j < 8; j++)
#pragma unroll
            for (int q = 0; q < 4; q++) acc[j][q] = 0.f;
    };
    // async-copy one 64x128 bf16 weight slab (row stride 272B in smem)
    auto cp_slab = [&](const unsigned* Wb, int slab, unsigned bufu) {
#pragma unroll
        for (int i = 0; i < 4; i++) {
            int c = tid + 256 * i;
            int row = c >> 4, c4 = c & 15;
            unsigned dstb = bufu + (unsigned)(row * 272 + c4 * 16);
            const unsigned* srcp = Wb + (slab * 64 + row) * 64 + c4 * 4;
            asm volatile("cp.async.cg.shared.global [%0], [%1], 16;"
                         :: "r"(dstb), "l"(srcp) : "memory");
        }
        asm volatile("cp.async.commit_group;" ::: "memory");
    };
    auto compute_tile = [&](unsigned abase, unsigned bbase, int kbase) {
        unsigned a[4];
        {
            int arow = wm + (lane & 7) + ((lane >> 3) & 1) * 8;
            int acol = kbase + (lane >> 4) * 8;
            ldm_x4(a[0], a[1], a[2], a[3], abase + (unsigned)(arow * STR + acol) * 2);
        }
        int krow = (kbase & 63) + (lane & 15);
        int cofs = (lane >> 4) * 8;
#pragma unroll
        for (int j = 0; j < 4; j++) {
            unsigned b[4];
            int n0 = wn + 16 * j;
            ldm_x4_t(b[0], b[1], b[2], b[3], bbase + (unsigned)(krow * STR + n0 + cofs) * 2);
            mma_bf16(acc[2 * j], a, b[0], b[1]);
            mma_bf16(acc[2 * j + 1], a, b[2], b[3]);
        }
    };
    auto gemm_layer = [&](unsigned abase, const unsigned* Wb) {
        zero_acc();
        cp_slab(Wb, 0, b0_u);
        asm volatile("cp.async.wait_group 0;" ::: "memory");
        __syncthreads();
        cp_slab(Wb, 1, b1_u);
#pragma unroll
        for (int ks = 0; ks < 4; ks++) compute_tile(abase, b0_u, ks * 16);
        asm volatile("cp.async.wait_group 0;" ::: "memory");
        __syncthreads();
#pragma unroll
        for (int ks = 0; ks < 4; ks++) compute_tile(abase, b1_u, 64 + ks * 16);
        __syncthreads();
    };
    auto conv_sE = [&] {
        for (int i = tid; i < 64 * 64; i += 256) {
            int row = i >> 6, cp = i & 63;
            sAew[row * 68 + cp] = pack_bf16(sE[row * STR + 2 * cp], sE[row * STR + 2 * cp + 1]);
        }
    };

    // one gated-MLP chain; leaves final raw L2 pre-activation in acc.
    auto run_chain = [&](const unsigned* wch, const float* NS, const float* ND,
                         const float* b1v) {
        gemm_layer(ae_u, wch);                      // L0 (A = edge tile)
#pragma unroll
        for (int nt = 0; nt < 8; nt++) {
            int gn = wn + nt * 8 + 2 * (lane & 3);
            float2 ns0 = v0 ? *(const float2*)(NS + (size_t)s0 * 128 + gn) : make_float2(0, 0);
            float2 nd0 = v0 ? *(const float2*)(ND + (size_t)d0 * 128 + gn) : make_float2(0, 0);
            float2 ns1 = v1 ? *(const float2*)(NS + (size_t)s1 * 128 + gn) : make_float2(0, 0);
            float2 nd1 = v1 ? *(const float2*)(ND + (size_t)d1 * 128 + gn) : make_float2(0, 0);
            sActw[rr0 * 68 + (gn >> 1)] =
                pack_bf16(siluf(acc[nt][0] + ns0.x + nd0.x), siluf(acc[nt][1] + ns0.y + nd0.y));
            sActw[(rr0 + 8) * 68 + (gn >> 1)] =
                pack_bf16(siluf(acc[nt][2] + ns1.x + nd1.x), siluf(acc[nt][3] + ns1.y + nd1.y));
        }
        gemm_layer(act_u, wch + 8192);              // L1
#pragma unroll
        for (int nt = 0; nt < 8; nt++) {
            int gn = wn + nt * 8 + 2 * (lane & 3);
            float bv0 = b1v[gn], bv1 = b1v[gn + 1];
            sActw[rr0 * 68 + (gn >> 1)] =
                pack_bf16(siluf(acc[nt][0] + bv0), siluf(acc[nt][1] + bv1));
            sActw[(rr0 + 8) * 68 + (gn >> 1)] =
                pack_bf16(siluf(acc[nt][2] + bv0), siluf(acc[nt][3] + bv1));
        }
        gemm_layer(act_u, wch + 16384);             // L2 -> raw acc
    };

    for (int br = 0; br < 2; br++) {
        const unsigned* wbr = wbase + (size_t)br * 49152;
        const float* bh1 = b1k + br * 128;
        const float* bg1 = gb1k + br * 128;
        const float* bh2 = b2k + br * 128;
        const float* bg2 = gb2k + br * 128;
        const float* NSh = g_nodepre + (size_t)(br * 4 + 0) * NN * 128;
        const float* NDh = g_nodepre + (size_t)(br * 4 + 1) * NN * 128;
        const float* NSg = g_nodepre + (size_t)(br * 4 + 2) * NN * 128;
        const float* NDg = g_nodepre + (size_t)(br * 4 + 3) * NN * 128;

        conv_sE();
        for (int i = tid; i < 9 * 128; i += 256) swt[i] = wtk[br * 9 * 128 + i];
        // ordering provided by first gemm_layer's internal barrier

        // h chain -> pack silu(h2) to bf16x2
        run_chain(wbr, NSh, NDh, bh1);
#pragma unroll
        for (int nt = 0; nt < 8; nt++) {
            int gn = wn + nt * 8 + 2 * (lane & 3);
            float bv0 = bh2[gn], bv1 = bh2[gn + 1];
            hpk[nt][0] = pack_bf16(siluf(acc[nt][0] + bv0), siluf(acc[nt][1] + bv1));
            hpk[nt][1] = pack_bf16(siluf(acc[nt][2] + bv0), siluf(acc[nt][3] + bv1));
        }
        // g chain (raw L2 in acc)
        run_chain(wbr + 24576, NSg, NDg, bg1);

        // ---- epilogue ----
        float rb0[9], rb1[9];
#pragma unroll
        for (int q = 0; q < 9; q++) {
            rb0[q] = v0 ? g_rbf[e0 * 9 + q] : 0.f;
            rb1[q] = v1 ? g_rbf[e1 * 9 + q] : 0.f;
        }
#pragma unroll
        for (int nt = 0; nt < 8; nt++) {
            int gn = wn + nt * 8 + 2 * (lane & 3);
            float w00 = 0.f, w01 = 0.f, w10 = 0.f, w11 = 0.f;
#pragma unroll
            for (int q = 0; q < 9; q++) {
                float wc0 = swt[q * 128 + gn], wc1 = swt[q * 128 + gn + 1];
                w00 = fmaf(rb0[q], wc0, w00);
                w01 = fmaf(rb0[q], wc1, w01);
                w10 = fmaf(rb1[q], wc0, w10);
                w11 = fmaf(rb1[q], wc1, w11);
            }
            float gb0v = bg2[gn], gb1v = bg2[gn + 1];
            float val0 = bf_lo(hpk[nt][0]) * sigf(acc[nt][0] + gb0v) * w00;
            float val1 = bf_hi(hpk[nt][0]) * sigf(acc[nt][1] + gb1v) * w01;
            float val2 = bf_lo(hpk[nt][1]) * sigf(acc[nt][2] + gb0v) * w10;
            float val3 = bf_hi(hpk[nt][1]) * sigf(acc[nt][3] + gb1v) * w11;
            if (br == 0) {
                if (v0) {
                    float n0v = sE[rr0 * STR + gn] + val0;
                    float n1v = sE[rr0 * STR + gn + 1] + val1;
                    sE[rr0 * STR + gn] = n0v;
                    sE[rr0 * STR + gn + 1] = n1v;
                    *(float2*)(g_edgefeat + (size_t)e0 * 128 + gn) = make_float2(n0v, n1v);
                }
                if (v1) {
                    float n2v = sE[(rr0 + 8) * STR + gn] + val2;
                    float n3v = sE[(rr0 + 8) * STR + gn + 1] + val3;
                    sE[(rr0 + 8) * STR + gn] = n2v;
                    sE[(rr0 + 8) * STR + gn + 1] = n3v;
                    *(float2*)(g_edgefeat + (size_t)e1 * 128 + gn) = make_float2(n2v, n3v);
                }
            } else {
                if (v0) {
                    atomicAdd(&g_nodefeat[(size_t)d0 * 128 + gn], val0);
                    atomicAdd(&g_nodefeat[(size_t)d0 * 128 + gn + 1], val1);
                }
                if (v1) {
                    atomicAdd(&g_nodefeat[(size_t)d1 * 128 + gn], val2);
                    atomicAdd(&g_nodefeat[(size_t)d1 * 128 + gn + 1], val3);
                }
            }
        }
        __syncthreads();
    }
}

// ---------------- readout -------------------------------------------------------
__global__ void k_mean() {
    int j = threadIdx.x;
    int b = blockIdx.x;
    float s = 0.f;
    for (int n = b * 125; n < b * 125 + 125; n++) s += g_nodefeat[n * 128 + j];
    atomicAdd(&g_mean[j], s);
}

__global__ void k_final(const float* __restrict__ fW0, const float* __restrict__ fb0,
                        const float* __restrict__ fW1, const float* __restrict__ fb1,
                        const float* __restrict__ fW2, const float* __restrict__ fb2,
                        float* __restrict__ out) {
    __shared__ float v[128], h0[128], h1[128], red[128];
    int j = threadIdx.x;
    v[j] = g_mean[j] / (float)NN;
    __syncthreads();
    float a = fb0[j];
    for (int i = 0; i < 128; i++) a = fmaf(v[i], fW0[i * 128 + j], a);
    h0[j] = siluf(a);
    __syncthreads();
    a = fb1[j];
    for (int i = 0; i < 128; i++) a = fmaf(h0[i], fW1[i * 128 + j], a);
    h1[j] = siluf(a);
    __syncthreads();
    red[j] = h1[j] * fW2[j];
    __syncthreads();
    for (int st = 64; st > 0; st >>= 1) {
        if (j < st) red[j] += red[j + st];
        __syncthreads();
    }
    if (j == 0) out[0] = red[0] + fb2[0];
}

// ---------------- host ----------------------------------------------------------
static double h_jl(int l, double x) {
    double s = sin(x), c = cos(x);
    if (l == 1) return s / (x * x) - c / x;
    if (l == 2) return (3.0 / (x * x * x) - 1.0 / x) * s - 3.0 * c / (x * x);
    return (15.0 / (x * x * x * x) - 6.0 / (x * x)) * s - (15.0 / (x * x * x) - 1.0 / x) * c;
}

extern "C" void kernel_launch(void* const* d_in, const int* in_sizes, int n_in,
                              void* d_out, int out_size) {
    const float* pos  = (const float*)d_in[0];
    const int* node_type = (const int*)d_in[1];
    const int* src  = (const int*)d_in[2];
    const int* dst  = (const int*)d_in[3];
    const int* t_src = (const int*)d_in[4];
    const int* t_dst = (const int*)d_in[5];
    const float* emb  = (const float*)d_in[6];
    const float* eW   = (const float*)d_in[7];
    const float* eb   = (const float*)d_in[8];
    const float* taW  = (const float*)d_in[9];
    const float* tab  = (const float*)d_in[10];
    const float* tbW  = (const float*)d_in[11];
    const float* tbWg = (const float*)d_in[12];
    const float* W0 = (const float*)d_in[13];  const float* b0 = (const float*)d_in[14];
    const float* W1 = (const float*)d_in[15];  const float* b1 = (const float*)d_in[16];
    const float* W2 = (const float*)d_in[17];  const float* b2 = (const float*)d_in[18];
    const float* gW0 = (const float*)d_in[19]; const float* gb0 = (const float*)d_in[20];
    const float* gW1 = (const float*)d_in[21]; const float* gb1 = (const float*)d_in[22];
    const float* gW2 = (const float*)d_in[23]; const float* gb2 = (const float*)d_in[24];
    const float* wt = (const float*)d_in[25];
    const float* fW0 = (const float*)d_in[26]; const float* fb0 = (const float*)d_in[27];
    const float* fW1 = (const float*)d_in[28]; const float* fb1 = (const float*)d_in[29];
    const float* fW2 = (const float*)d_in[30]; const float* fb2 = (const float*)d_in[31];
    float* out = (float*)d_out;

    Scales sc;
    {
        const double roots[9] = {
            3.141592653589793, 6.283185307179586, 9.42477796076938,
            4.493409457909064, 7.725251836937707, 10.904121659428899,
            5.763459196894550, 9.095011330476355, 12.322940970566582};
        double fac = sqrt(2.0 / 125.0);
        for (int l = 0; l < 3; l++)
            for (int n = 0; n < 3; n++)
                sc.v[l * 3 + n] = (float)(fac / fabs(h_jl(l + 1, roots[l * 3 + n])));
    }

    unsigned* pwb;
    cudaGetSymbolAddress((void**)&pwb, g_wbf16);

    cudaFuncSetAttribute(fused_block, cudaFuncAttributeMaxDynamicSharedMemorySize, FUSED_SMEM);

    // Launch order puts fused_block (k=0) at position 4 — the launch ncu captures.
    int n0 = NE + NN * 128 + 128 + CONVW_N;
    k_setup0<<<(n0 + 255) / 256, 256>>>(pos, src, dst, node_type, emb, sc,
                                        W0, W1, W2, gW0, gW1, gW2);
    k_block_setup<<<NG_BLOCKS + AT_BLOCKS + ZB_BLOCKS, 256>>>(W0, gW0, b0, gb0, taW, tab, 0);
    int n1 = NT + NE * 128;
    k_setup1<<<(n1 + 255) / 256, 256>>>(t_src, t_dst, dst, eW, eb);  // includes k=0 tripacc

    for (int k = 0; k < 3; k++) {
        if (k > 0) {
            k_block_setup<<<NG_BLOCKS + AT_BLOCKS + ZB_BLOCKS, 256>>>(W0, gW0, b0, gb0, taW, tab, k);
            k_tripacc<<<(NT + 255) / 256, 256>>>(t_src);
        }
        fused_block<<<FUSED_GRID, 256, FUSED_SMEM>>>(
            src, dst, tbW + k * 9 * 128, tbWg + k * 9 * 128,
            pwb + (size_t)k * 2 * 49152,
            b1 + k * 2 * 128, b2 + k * 2 * 128,
            gb1 + k * 2 * 128, gb2 + k * 2 * 128,
            wt + k * 2 * 9 * 128);
    }
    k_mean<<<40, 128>>>();
    k_final<<<1, 128>>>(fW0, fb0, fW1, fb1, fW2, fb2, out);
}

// round 15
// speedup vs baseline: 1.0886x; 1.0412x over previous
#include <cuda_runtime.h>
#include <math.h>

#define NN 5000
#define NE 60000
#define NT 400000

// ---------------- scratch (device globals) --------------------------------------
__device__ float g_bondvec[NE * 3];
__device__ float g_dist[NE];
__device__ float g_rbf[NE * 9];
__device__ float g_cut3[NE];
__device__ float g_tbw[NT * 9];
__device__ int   g_endatom[NT];
__device__ float g_nodefeat[NN * 128];
__device__ float g_edgefeat[NE * 128];
__device__ float g_atoms[NN * 9];
__device__ float g_nb[NE * 9];
__device__ float g_nodepre[8 * NN * 128];   // slices: br*4 + chain*2 + side
__device__ float g_mean[128];
__device__ unsigned g_wbf16[6 * 6 * 128 * 64];  // [kbr][layer:{h0e,h1,h2,g0e,g1,g2}][128][64w]

struct Scales { float v[9]; };

__constant__ float c_roots[9] = {
    3.141592653589793f, 6.283185307179586f, 9.42477796076938f,
    4.493409457909064f, 7.725251836937707f, 10.904121659428899f,
    5.763459196894550f, 9.095011330476355f, 12.322940970566582f};

#define Y00F 0.28209479177387814f
#define Y10F 0.4886025119029199f
#define Y20F 0.31539156525252005f

__device__ __forceinline__ float siluf(float v) { return v / (1.f + expf(-v)); }
__device__ __forceinline__ float sigf(float v)  { return 1.f / (1.f + expf(-v)); }

__device__ __forceinline__ float jlf(int l, float x) {
    float s, c;
    sincosf(x, &s, &c);
    float inv = 1.f / x;
    if (l == 0) return s * inv;
    if (l == 1) return (s * inv - c) * inv;
    return (3.f * inv * inv - 1.f) * s * inv - 3.f * c * inv * inv;
}

// ---------------- mma / pack primitives -----------------------------------------
__device__ __forceinline__ unsigned f2tf(float x) {
    unsigned u;
    asm("cvt.rna.tf32.f32 %0, %1;" : "=r"(u) : "f"(x));
    return u;
}
__device__ __forceinline__ void mma_tf32(float* d, const unsigned* a, unsigned b0, unsigned b1) {
    asm volatile(
        "mma.sync.aligned.m16n8k8.row.col.f32.tf32.tf32.f32 "
        "{%0,%1,%2,%3}, {%4,%5,%6,%7}, {%8,%9}, {%0,%1,%2,%3};"
        : "+f"(d[0]), "+f"(d[1]), "+f"(d[2]), "+f"(d[3])
        : "r"(a[0]), "r"(a[1]), "r"(a[2]), "r"(a[3]), "r"(b0), "r"(b1));
}
__device__ __forceinline__ unsigned pack_bf16(float lo, float hi) {
    unsigned r;
    asm("cvt.rn.bf16x2.f32 %0, %1, %2;" : "=r"(r) : "f"(hi), "f"(lo));
    return r;
}
__device__ __forceinline__ float bf_lo(unsigned p) { return __uint_as_float(p << 16); }
__device__ __forceinline__ float bf_hi(unsigned p) { return __uint_as_float(p & 0xffff0000u); }
__device__ __forceinline__ void ldm_x4(unsigned& r0, unsigned& r1, unsigned& r2, unsigned& r3,
                                       unsigned addr) {
    asm volatile("ldmatrix.sync.aligned.m8n8.x4.shared.b16 {%0,%1,%2,%3}, [%4];"
                 : "=r"(r0), "=r"(r1), "=r"(r2), "=r"(r3) : "r"(addr));
}
__device__ __forceinline__ void ldm_x4_t(unsigned& r0, unsigned& r1, unsigned& r2, unsigned& r3,
                                         unsigned addr) {
    asm volatile("ldmatrix.sync.aligned.m8n8.x4.trans.shared.b16 {%0,%1,%2,%3}, [%4];"
                 : "=r"(r0), "=r"(r1), "=r"(r2), "=r"(r3) : "r"(addr));
}
__device__ __forceinline__ void mma_bf16(float* d, const unsigned* a, unsigned b0, unsigned b1) {
    asm volatile(
        "mma.sync.aligned.m16n8k16.row.col.f32.bf16.bf16.f32 "
        "{%0,%1,%2,%3}, {%4,%5,%6,%7}, {%8,%9}, {%0,%1,%2,%3};"
        : "+f"(d[0]), "+f"(d[1]), "+f"(d[2]), "+f"(d[3])
        : "r"(a[0]), "r"(a[1]), "r"(a[2]), "r"(a[3]), "r"(b0), "r"(b1));
}

// ---------------- kernel 0: geom + nodeinit + zero mean + weight conv -----------
#define CONVW_N (6 * 6 * 8192)
__global__ void k_setup0(const float* __restrict__ pos, const int* __restrict__ src,
                         const int* __restrict__ dst, const int* __restrict__ node_type,
                         const float* __restrict__ emb, Scales sc,
                         const float* __restrict__ W0, const float* __restrict__ W1,
                         const float* __restrict__ W2, const float* __restrict__ gW0,
                         const float* __restrict__ gW1, const float* __restrict__ gW2) {
    int idx = blockIdx.x * blockDim.x + threadIdx.x;
    if (idx < NE) {
        int e = idx;
        int s = src[e], d = dst[e];
        float dx = pos[d * 3 + 0] - pos[s * 3 + 0];
        float dy = pos[d * 3 + 1] - pos[s * 3 + 1];
        float dz = pos[d * 3 + 2] - pos[s * 3 + 2];
        float dist = sqrtf(dx * dx + dy * dy + dz * dz + 1e-12f);
        g_bondvec[e * 3 + 0] = dx;
        g_bondvec[e * 3 + 1] = dy;
        g_bondvec[e * 3 + 2] = dz;
        g_dist[e] = dist;
#pragma unroll
        for (int l = 0; l < 3; l++)
#pragma unroll
            for (int n = 0; n < 3; n++)
                g_rbf[e * 9 + l * 3 + n] = jlf(l, dist * c_roots[l * 3 + n] * 0.2f) * sc.v[l * 3 + n];
        float xx = dist * 0.25f;
        float x2 = xx * xx, x3 = x2 * xx;
        g_cut3[e] = 1.f - 6.f * x3 * x2 + 15.f * x2 * x2 - 10.f * x3;
    } else if (idx < NE + NN * 128) {
        int i = idx - NE;
        int n = i >> 7, c = i & 127;
        g_nodefeat[i] = emb[node_type[n] * 128 + c];
    } else if (idx < NE + NN * 128 + 128) {
        g_mean[idx - NE - NN * 128] = 0.f;
    } else if (idx < NE + NN * 128 + 128 + CONVW_N) {
        int w = idx - (NE + NN * 128 + 128);
        int kbr = w / 49152;
        int rem = w - kbr * 49152;
        int l = rem / 8192;
        int pos_ = rem - l * 8192;
        int row = pos_ >> 6, cw = pos_ & 63;
        const float* srcw;
        if (l == 0)      srcw = W0  + (size_t)kbr * 384 * 128 + 256 * 128;
        else if (l == 1) srcw = W1  + (size_t)kbr * 128 * 128;
        else if (l == 2) srcw = W2  + (size_t)kbr * 128 * 128;
        else if (l == 3) srcw = gW0 + (size_t)kbr * 384 * 128 + 256 * 128;
        else if (l == 4) srcw = gW1 + (size_t)kbr * 128 * 128;
        else             srcw = gW2 + (size_t)kbr * 128 * 128;
        float2 v = *(const float2*)(srcw + row * 128 + cw * 2);
        g_wbf16[w] = pack_bf16(v.x, v.y);
    }
}

// ---------------- kernel 1: triplet (+fused k=0 scatter) + edgeemb --------------
// g_nb must be zeroed and g_atoms (k=0) computed BEFORE this kernel (k_block_setup).
__global__ void k_setup1(const int* __restrict__ t_src, const int* __restrict__ t_dst,
                         const int* __restrict__ dst,
                         const float* __restrict__ W, const float* __restrict__ b) {
    int idx = blockIdx.x * blockDim.x + threadIdx.x;
    if (idx < NT) {
        int t = idx;
        int es = t_src[t], ed = t_dst[t];
        float v1x = g_bondvec[es * 3 + 0], v1y = g_bondvec[es * 3 + 1], v1z = g_bondvec[es * 3 + 2];
        float v2x = g_bondvec[ed * 3 + 0], v2y = g_bondvec[ed * 3 + 1], v2z = g_bondvec[ed * 3 + 2];
        float cost = (v1x * v2x + v1y * v2y + v1z * v2z) / (g_dist[es] * g_dist[ed]);
        float shf[3];
        shf[0] = Y00F;
        shf[1] = Y10F * cost;
        shf[2] = Y20F * (3.f * cost * cost - 1.f);
        float tw = g_cut3[es] * g_cut3[ed];
        int ea = dst[ed];
        g_endatom[t] = ea;
        float tb[9];
#pragma unroll
        for (int l = 0; l < 3; l++)
#pragma unroll
            for (int n = 0; n < 3; n++)
                tb[l * 3 + n] = g_rbf[ed * 9 + l * 3 + n] * shf[l] * tw;
#pragma unroll
        for (int q = 0; q < 9; q++) {
            g_tbw[t * 9 + q] = tb[q];
            atomicAdd(&g_nb[es * 9 + q], tb[q] * g_atoms[ea * 9 + q]);  // k=0 tripacc fused
        }
    } else if (idx < NT + NE * 128) {
        int i = idx - NT;
        int e = i >> 7, j = i & 127;
        float acc = b[j];
#pragma unroll
        for (int q = 0; q < 9; q++) acc = fmaf(g_rbf[e * 9 + q], W[q * 128 + j], acc);
        g_edgefeat[i] = siluf(acc);
    }
}

// ---------------- kernel 2: nodegemm(8 slices, tf32) + atoms + zero_nb ----------
#define NG_BLOCKS 320
#define AT_BLOCKS 176
#define ZB_BLOCKS 2110

__global__ void __launch_bounds__(256) k_block_setup(
    const float* __restrict__ W0, const float* __restrict__ gW0,
    const float* __restrict__ b0, const float* __restrict__ gb0,
    const float* __restrict__ taW, const float* __restrict__ tab, int k) {
    int blk = blockIdx.x;
    if (blk < NG_BLOCKS) {
        __shared__ unsigned sA[128 * 40];
        __shared__ unsigned sB[32 * 136];
        int slice = blk & 7, mt = blk >> 3;
        int br = slice >> 2, chain = (slice >> 1) & 1, side = slice & 1;
        const float* Wbase = (chain ? gW0 : W0) + (size_t)(k * 2 + br) * 384 * 128 + side * 128 * 128;
        const float* bias = side == 0 ? ((chain ? gb0 : b0) + (k * 2 + br) * 128) : nullptr;
        float* out = g_nodepre + (size_t)slice * NN * 128;
        const float* A = g_nodefeat;
        int bm = mt * 128;

        const int tid = threadIdx.x;
        const int lane = tid & 31, wid = tid >> 5;
        const int wm = (wid & 3) * 32, wn = (wid >> 2) * 64;
        float acc[2][8][4];
#pragma unroll
        for (int i = 0; i < 2; i++)
#pragma unroll
            for (int j = 0; j < 8; j++)
#pragma unroll
                for (int q = 0; q < 4; q++) acc[i][j][q] = 0.f;

        const int r0 = tid >> 3, c4 = tid & 7;
        const int bk0 = tid >> 5, bn4 = tid & 31;
        for (int kt = 0; kt < 4; kt++) {
#pragma unroll
            for (int i = 0; i < 4; i++) {
                int gm = bm + r0 + 32 * i;
                float4 v = make_float4(0.f, 0.f, 0.f, 0.f);
                if (gm < NN) v = *(const float4*)(A + (size_t)gm * 128 + kt * 32 + c4 * 4);
                uint4 u;
                u.x = f2tf(v.x); u.y = f2tf(v.y); u.z = f2tf(v.z); u.w = f2tf(v.w);
                *(uint4*)&sA[(r0 + 32 * i) * 40 + c4 * 4] = u;
            }
#pragma unroll
            for (int i = 0; i < 4; i++) {
                float4 v = *(const float4*)(Wbase + (size_t)(kt * 32 + bk0 + 8 * i) * 128 + bn4 * 4);
                uint4 u;
                u.x = f2tf(v.x); u.y = f2tf(v.y); u.z = f2tf(v.z); u.w = f2tf(v.w);
                *(uint4*)&sB[(bk0 + 8 * i) * 136 + bn4 * 4] = u;
            }
            __syncthreads();
#pragma unroll
            for (int ks = 0; ks < 4; ks++) {
                unsigned a[2][4];
                int arow = wm + (lane >> 2);
                int acol = ks * 8 + (lane & 3);
#pragma unroll
                for (int m2 = 0; m2 < 2; m2++) {
                    int rr = arow + m2 * 16;
                    a[m2][0] = sA[rr * 40 + acol];
                    a[m2][1] = sA[(rr + 8) * 40 + acol];
                    a[m2][2] = sA[rr * 40 + acol + 4];
                    a[m2][3] = sA[(rr + 8) * 40 + acol + 4];
                }
                int bro = (ks * 8 + (lane & 3)) * 136 + wn + (lane >> 2);
#pragma unroll
                for (int nt = 0; nt < 8; nt++) {
                    unsigned b0r = sB[bro + nt * 8];
                    unsigned b1r = sB[bro + 4 * 136 + nt * 8];
                    mma_tf32(acc[0][nt], a[0], b0r, b1r);
                    mma_tf32(acc[1][nt], a[1], b0r, b1r);
                }
            }
            __syncthreads();
        }
#pragma unroll
        for (int m2 = 0; m2 < 2; m2++) {
#pragma unroll
            for (int nt = 0; nt < 8; nt++) {
                int gn = wn + nt * 8 + 2 * (lane & 3);
                float bv0 = bias ? bias[gn] : 0.f;
                float bv1 = bias ? bias[gn + 1] : 0.f;
                int gm0 = bm + wm + m2 * 16 + (lane >> 2);
                if (gm0 < NN)
                    *(float2*)(out + (size_t)gm0 * 128 + gn) =
                        make_float2(acc[m2][nt][0] + bv0, acc[m2][nt][1] + bv1);
                int gm1 = gm0 + 8;
                if (gm1 < NN)
                    *(float2*)(out + (size_t)gm1 * 128 + gn) =
                        make_float2(acc[m2][nt][2] + bv0, acc[m2][nt][3] + bv1);
            }
        }
    } else if (blk < NG_BLOCKS + AT_BLOCKS) {
        int idx = (blk - NG_BLOCKS) * 256 + threadIdx.x;
        if (idx < NN * 9) {
            int n = idx / 9, j = idx % 9;
            float acc = tab[k * 9 + j];
            const float* nf = &g_nodefeat[n * 128];
            const float* W = taW + (size_t)k * 128 * 9;
#pragma unroll 8
            for (int i = 0; i < 128; i++) acc = fmaf(nf[i], W[i * 9 + j], acc);
            g_atoms[idx] = sigf(acc);
        }
    } else {
        int idx = (blk - NG_BLOCKS - AT_BLOCKS) * 256 + threadIdx.x;
        if (idx < NE * 9) g_nb[idx] = 0.f;
    }
}

// ---------------- tripacc (k=1,2 only; k=0 fused into setup1) -------------------
__global__ void k_tripacc(const int* __restrict__ t_src) {
    int t = blockIdx.x * blockDim.x + threadIdx.x;
    if (t >= NT) return;
    int es = t_src[t];
    int ea = g_endatom[t];
#pragma unroll
    for (int q = 0; q < 9; q++)
        atomicAdd(&g_nb[es * 9 + q], g_tbw[t * 9 + q] * g_atoms[ea * 9 + q]);
}

// ---------------- fused megakernel: tb-update + both branches (BM=64) -----------
// smem bytes: sAct @0 (17408) | sAe @17408 (17408) | sB0 @34816 (17408) |
//             sB1 @52224 (17408) | swt @69632 (4608)  => 74240  (3 CTAs/SM)
#define FUSED_SMEM 74240
#define FUSED_GRID ((NE + 63) / 64)
#define STR 136

__global__ void __launch_bounds__(256, 3) fused_block(
    const int* __restrict__ src, const int* __restrict__ dst,
    const float* __restrict__ Wbk, const float* __restrict__ Wgk,
    const unsigned* __restrict__ wbase,                 // bf16 weights, this k (2 branches)
    const float* __restrict__ b1k, const float* __restrict__ b2k,
    const float* __restrict__ gb1k, const float* __restrict__ gb2k,
    const float* __restrict__ wtk) {
    extern __shared__ char smem_raw[];
    unsigned* sActw = (unsigned*)(smem_raw);
    unsigned* sAew  = (unsigned*)(smem_raw + 17408);
    float*    swt   = (float*)(smem_raw + 69632);

    const unsigned act_u = (unsigned)__cvta_generic_to_shared(sActw);
    const unsigned ae_u  = (unsigned)__cvta_generic_to_shared(sAew);
    const unsigned b0_u  = (unsigned)__cvta_generic_to_shared(smem_raw + 34816);
    const unsigned b1_u  = (unsigned)__cvta_generic_to_shared(smem_raw + 52224);

    const int tid = threadIdx.x;
    const int lane = tid & 31, wid = tid >> 5;
    const int wm = (wid & 3) * 16, wn = (wid >> 2) * 64;
    const int bm = blockIdx.x * 64;

    const int rr0 = wm + (lane >> 2);
    const int e0 = bm + rr0, e1 = e0 + 8;
    const bool v0 = e0 < NE, v1 = e1 < NE;
    const int s0 = v0 ? src[e0] : 0, d0 = v0 ? dst[e0] : 0;
    const int s1 = v1 ? src[e1] : 0, d1 = v1 ? dst[e1] : 0;

    // ---- stage A: three-body edge update -> g_edgefeat (fp32) + sAe (bf16) -----
    {
        float* sWb = (float*)sActw;                    // scratch (9x128)
        float* sWg = (float*)(smem_raw + 34816);       // scratch in sB0 region
        for (int i = tid; i < 9 * 128; i += 256) { sWb[i] = Wbk[i]; sWg[i] = Wgk[i]; }
        __syncthreads();
        for (int i = tid; i < 64 * 64; i += 256) {
            int row = i >> 6, cp = i & 63;
            int e = bm + row;
            float nv0 = 0.f, nv1 = 0.f;
            if (e < NE) {
                int c0 = 2 * cp;
                float s10 = 0.f, s20 = 0.f, s11 = 0.f, s21 = 0.f;
#pragma unroll
                for (int q = 0; q < 9; q++) {
                    float nv = g_nb[e * 9 + q];
                    s10 = fmaf(nv, sWb[q * 128 + c0], s10);
                    s20 = fmaf(nv, sWg[q * 128 + c0], s20);
                    s11 = fmaf(nv, sWb[q * 128 + c0 + 1], s11);
                    s21 = fmaf(nv, sWg[q * 128 + c0 + 1], s21);
                }
                float2 ef = *(const float2*)(g_edgefeat + (size_t)e * 128 + c0);
                nv0 = ef.x + siluf(s10) * sigf(s20);
                nv1 = ef.y + siluf(s11) * sigf(s21);
                *(float2*)(g_edgefeat + (size_t)e * 128 + c0) = make_float2(nv0, nv1);
            }
            sAew[row * 68 + cp] = pack_bf16(nv0, nv1);
        }
        __syncthreads();   // sWb/sWg reads done before sB0 reuse; sAe visible
    }

    float acc[8][4];
    unsigned hpk[8][2];   // silu(h2) packed bf16x2

    auto zero_acc = [&] {
#pragma unroll
        for (int j = 0; j < 8; j++)
#pragma unroll
            for (int q = 0; q < 4; q++) acc[j][q] = 0.f;
    };
    // async-copy one 64x128 bf16 weight slab (row stride 272B in smem)
    auto cp_slab = [&](const unsigned* Wb, int slab, unsigned bufu) {
#pragma unroll
        for (int i = 0; i < 4; i++) {
            int c = tid + 256 * i;
            int row = c >> 4, c4 = c & 15;
            unsigned dstb = bufu + (unsigned)(row * 272 + c4 * 16);
            const unsigned* srcp = Wb + (slab * 64 + row) * 64 + c4 * 4;
            asm volatile("cp.async.cg.shared.global [%0], [%1], 16;"
                         :: "r"(dstb), "l"(srcp) : "memory");
        }
        asm volatile("cp.async.commit_group;" ::: "memory");
    };
    auto compute_tile = [&](unsigned abase, unsigned bbase, int kbase) {
        unsigned a[4];
        {
            int arow = wm + (lane & 7) + ((lane >> 3) & 1) * 8;
            int acol = kbase + (lane >> 4) * 8;
            ldm_x4(a[0], a[1], a[2], a[3], abase + (unsigned)(arow * STR + acol) * 2);
        }
        int krow = (kbase & 63) + (lane & 15);
        int cofs = (lane >> 4) * 8;
#pragma unroll
        for (int j = 0; j < 4; j++) {
            unsigned b[4];
            int n0 = wn + 16 * j;
            ldm_x4_t(b[0], b[1], b[2], b[3], bbase + (unsigned)(krow * STR + n0 + cofs) * 2);
            mma_bf16(acc[2 * j], a, b[0], b[1]);
            mma_bf16(acc[2 * j + 1], a, b[2], b[3]);
        }
    };
    auto gemm_layer = [&](unsigned abase, const unsigned* Wb) {
        zero_acc();
        cp_slab(Wb, 0, b0_u);
        asm volatile("cp.async.wait_group 0;" ::: "memory");
        __syncthreads();
        cp_slab(Wb, 1, b1_u);
#pragma unroll
        for (int ks = 0; ks < 4; ks++) compute_tile(abase, b0_u, ks * 16);
        asm volatile("cp.async.wait_group 0;" ::: "memory");
        __syncthreads();
#pragma unroll
        for (int ks = 0; ks < 4; ks++) compute_tile(abase, b1_u, 64 + ks * 16);
        __syncthreads();
    };

    // one gated-MLP chain; leaves final raw L2 pre-activation in acc.
    auto run_chain = [&](const unsigned* wch, const float* NS, const float* ND,
                         const float* b1v) {
        gemm_layer(ae_u, wch);                      // L0 (A = edge tile)
#pragma unroll
        for (int nt = 0; nt < 8; nt++) {
            int gn = wn + nt * 8 + 2 * (lane & 3);
            float2 ns0 = v0 ? *(const float2*)(NS + (size_t)s0 * 128 + gn) : make_float2(0, 0);
            float2 nd0 = v0 ? *(const float2*)(ND + (size_t)d0 * 128 + gn) : make_float2(0, 0);
            float2 ns1 = v1 ? *(const float2*)(NS + (size_t)s1 * 128 + gn) : make_float2(0, 0);
            float2 nd1 = v1 ? *(const float2*)(ND + (size_t)d1 * 128 + gn) : make_float2(0, 0);
            sActw[rr0 * 68 + (gn >> 1)] =
                pack_bf16(siluf(acc[nt][0] + ns0.x + nd0.x), siluf(acc[nt][1] + ns0.y + nd0.y));
            sActw[(rr0 + 8) * 68 + (gn >> 1)] =
                pack_bf16(siluf(acc[nt][2] + ns1.x + nd1.x), siluf(acc[nt][3] + ns1.y + nd1.y));
        }
        gemm_layer(act_u, wch + 8192);              // L1
#pragma unroll
        for (int nt = 0; nt < 8; nt++) {
            int gn = wn + nt * 8 + 2 * (lane & 3);
            float bv0 = b1v[gn], bv1 = b1v[gn + 1];
            sActw[rr0 * 68 + (gn >> 1)] =
                pack_bf16(siluf(acc[nt][0] + bv0), siluf(acc[nt][1] + bv1));
            sActw[(rr0 + 8) * 68 + (gn >> 1)] =
                pack_bf16(siluf(acc[nt][2] + bv0), siluf(acc[nt][3] + bv1));
        }
        gemm_layer(act_u, wch + 16384);             // L2 -> raw acc
    };

    for (int br = 0; br < 2; br++) {
        const unsigned* wbr = wbase + (size_t)br * 49152;
        const float* bh1 = b1k + br * 128;
        const float* bg1 = gb1k + br * 128;
        const float* bh2 = b2k + br * 128;
        const float* bg2 = gb2k + br * 128;
        const float* NSh = g_nodepre + (size_t)(br * 4 + 0) * NN * 128;
        const float* NDh = g_nodepre + (size_t)(br * 4 + 1) * NN * 128;
        const float* NSg = g_nodepre + (size_t)(br * 4 + 2) * NN * 128;
        const float* NDg = g_nodepre + (size_t)(br * 4 + 3) * NN * 128;

        for (int i = tid; i < 9 * 128; i += 256) swt[i] = wtk[br * 9 * 128 + i];
        // ordering provided by first gemm_layer's internal barrier

        // h chain -> pack silu(h2) to bf16x2
        run_chain(wbr, NSh, NDh, bh1);
#pragma unroll
        for (int nt = 0; nt < 8; nt++) {
            int gn = wn + nt * 8 + 2 * (lane & 3);
            float bv0 = bh2[gn], bv1 = bh2[gn + 1];
            hpk[nt][0] = pack_bf16(siluf(acc[nt][0] + bv0), siluf(acc[nt][1] + bv1));
            hpk[nt][1] = pack_bf16(siluf(acc[nt][2] + bv0), siluf(acc[nt][3] + bv1));
        }
        // g chain (raw L2 in acc)
        run_chain(wbr + 24576, NSg, NDg, bg1);

        // ---- epilogue ----
        float rb0[9], rb1[9];
#pragma unroll
        for (int q = 0; q < 9; q++) {
            rb0[q] = v0 ? g_rbf[e0 * 9 + q] : 0.f;
            rb1[q] = v1 ? g_rbf[e1 * 9 + q] : 0.f;
        }
#pragma unroll
        for (int nt = 0; nt < 8; nt++) {
            int gn = wn + nt * 8 + 2 * (lane & 3);
            float w00 = 0.f, w01 = 0.f, w10 = 0.f, w11 = 0.f;
#pragma unroll
            for (int q = 0; q < 9; q++) {
                float wc0 = swt[q * 128 + gn], wc1 = swt[q * 128 + gn + 1];
                w00 = fmaf(rb0[q], wc0, w00);
                w01 = fmaf(rb0[q], wc1, w01);
                w10 = fmaf(rb1[q], wc0, w10);
                w11 = fmaf(rb1[q], wc1, w11);
            }
            float gb0v = bg2[gn], gb1v = bg2[gn + 1];
            float val0 = bf_lo(hpk[nt][0]) * sigf(acc[nt][0] + gb0v) * w00;
            float val1 = bf_hi(hpk[nt][0]) * sigf(acc[nt][1] + gb1v) * w01;
            float val2 = bf_lo(hpk[nt][1]) * sigf(acc[nt][2] + gb0v) * w10;
            float val3 = bf_hi(hpk[nt][1]) * sigf(acc[nt][3] + gb1v) * w11;
            if (br == 0) {
                if (v0) {
                    float2 base = *(const float2*)(g_edgefeat + (size_t)e0 * 128 + gn);
                    float n0v = base.x + val0, n1v = base.y + val1;
                    *(float2*)(g_edgefeat + (size_t)e0 * 128 + gn) = make_float2(n0v, n1v);
                    sAew[rr0 * 68 + (gn >> 1)] = pack_bf16(n0v, n1v);
                }
                if (v1) {
                    float2 base = *(const float2*)(g_edgefeat + (size_t)e1 * 128 + gn);
                    float n2v = base.x + val2, n3v = base.y + val3;
                    *(float2*)(g_edgefeat + (size_t)e1 * 128 + gn) = make_float2(n2v, n3v);
                    sAew[(rr0 + 8) * 68 + (gn >> 1)] = pack_bf16(n2v, n3v);
                }
            } else {
                if (v0) {
                    atomicAdd(&g_nodefeat[(size_t)d0 * 128 + gn], val0);
                    atomicAdd(&g_nodefeat[(size_t)d0 * 128 + gn + 1], val1);
                }
                if (v1) {
                    atomicAdd(&g_nodefeat[(size_t)d1 * 128 + gn], val2);
                    atomicAdd(&g_nodefeat[(size_t)d1 * 128 + gn + 1], val3);
                }
            }
        }
        __syncthreads();   // sAe update visible before br=1 L0 reads it
    }
}

// ---------------- readout -------------------------------------------------------
__global__ void k_mean() {
    int j = threadIdx.x;
    int b = blockIdx.x;
    float s = 0.f;
    for (int n = b * 125; n < b * 125 + 125; n++) s += g_nodefeat[n * 128 + j];
    atomicAdd(&g_mean[j], s);
}

__global__ void k_final(const float* __restrict__ fW0, const float* __restrict__ fb0,
                        const float* __restrict__ fW1, const float* __restrict__ fb1,
                        const float* __restrict__ fW2, const float* __restrict__ fb2,
                        float* __restrict__ out) {
    __shared__ float v[128], h0[128], h1[128], red[128];
    int j = threadIdx.x;
    v[j] = g_mean[j] / (float)NN;
    __syncthreads();
    float a = fb0[j];
    for (int i = 0; i < 128; i++) a = fmaf(v[i], fW0[i * 128 + j], a);
    h0[j] = siluf(a);
    __syncthreads();
    a = fb1[j];
    for (int i = 0; i < 128; i++) a = fmaf(h0[i], fW1[i * 128 + j], a);
    h1[j] = siluf(a);
    __syncthreads();
    red[j] = h1[j] * fW2[j];
    __syncthreads();
    for (int st = 64; st > 0; st >>= 1) {
        if (j < st) red[j] += red[j + st];
        __syncthreads();
    }
    if (j == 0) out[0] = red[0] + fb2[0];
}

// ---------------- host ----------------------------------------------------------
static double h_jl(int l, double x) {
    double s = sin(x), c = cos(x);
    if (l == 1) return s / (x * x) - c / x;
    if (l == 2) return (3.0 / (x * x * x) - 1.0 / x) * s - 3.0 * c / (x * x);
    return (15.0 / (x * x * x * x) - 6.0 / (x * x)) * s - (15.0 / (x * x * x) - 1.0 / x) * c;
}

extern "C" void kernel_launch(void* const* d_in, const int* in_sizes, int n_in,
                              void* d_out, int out_size) {
    const float* pos  = (const float*)d_in[0];
    const int* node_type = (const int*)d_in[1];
    const int* src  = (const int*)d_in[2];
    const int* dst  = (const int*)d_in[3];
    const int* t_src = (const int*)d_in[4];
    const int* t_dst = (const int*)d_in[5];
    const float* emb  = (const float*)d_in[6];
    const float* eW   = (const float*)d_in[7];
    const float* eb   = (const float*)d_in[8];
    const float* taW  = (const float*)d_in[9];
    const float* tab  = (const float*)d_in[10];
    const float* tbW  = (const float*)d_in[11];
    const float* tbWg = (const float*)d_in[12];
    const float* W0 = (const float*)d_in[13];  const float* b0 = (const float*)d_in[14];
    const float* W1 = (const float*)d_in[15];  const float* b1 = (const float*)d_in[16];
    const float* W2 = (const float*)d_in[17];  const float* b2 = (const float*)d_in[18];
    const float* gW0 = (const float*)d_in[19]; const float* gb0 = (const float*)d_in[20];
    const float* gW1 = (const float*)d_in[21]; const float* gb1 = (const float*)d_in[22];
    const float* gW2 = (const float*)d_in[23]; const float* gb2 = (const float*)d_in[24];
    const float* wt = (const float*)d_in[25];
    const float* fW0 = (const float*)d_in[26]; const float* fb0 = (const float*)d_in[27];
    const float* fW1 = (const float*)d_in[28]; const float* fb1 = (const float*)d_in[29];
    const float* fW2 = (const float*)d_in[30]; const float* fb2 = (const float*)d_in[31];
    float* out = (float*)d_out;

    Scales sc;
    {
        const double roots[9] = {
            3.141592653589793, 6.283185307179586, 9.42477796076938,
            4.493409457909064, 7.725251836937707, 10.904121659428899,
            5.763459196894550, 9.095011330476355, 12.322940970566582};
        double fac = sqrt(2.0 / 125.0);
        for (int l = 0; l < 3; l++)
            for (int n = 0; n < 3; n++)
                sc.v[l * 3 + n] = (float)(fac / fabs(h_jl(l + 1, roots[l * 3 + n])));
    }

    unsigned* pwb;
    cudaGetSymbolAddress((void**)&pwb, g_wbf16);

    cudaFuncSetAttribute(fused_block, cudaFuncAttributeMaxDynamicSharedMemorySize, FUSED_SMEM);

    int n0 = NE + NN * 128 + 128 + CONVW_N;
    k_setup0<<<(n0 + 255) / 256, 256>>>(pos, src, dst, node_type, emb, sc,
                                        W0, W1, W2, gW0, gW1, gW2);
    k_block_setup<<<NG_BLOCKS + AT_BLOCKS + ZB_BLOCKS, 256>>>(W0, gW0, b0, gb0, taW, tab, 0);
    int n1 = NT + NE * 128;
    k_setup1<<<(n1 + 255) / 256, 256>>>(t_src, t_dst, dst, eW, eb);  // includes k=0 tripacc

    for (int k = 0; k < 3; k++) {
        if (k > 0) {
            k_block_setup<<<NG_BLOCKS + AT_BLOCKS + ZB_BLOCKS, 256>>>(W0, gW0, b0, gb0, taW, tab, k);
            k_tripacc<<<(NT + 255) / 256, 256>>>(t_src);
        }
        fused_block<<<FUSED_GRID, 256, FUSED_SMEM>>>(
            src, dst, tbW + k * 9 * 128, tbWg + k * 9 * 128,
            pwb + (size_t)k * 2 * 49152,
            b1 + k * 2 * 128, b2 + k * 2 * 128,
            gb1 + k * 2 * 128, gb2 + k * 2 * 128,
            wt + k * 2 * 9 * 128);
    }
    k_mean<<<40, 128>>>();
    k_final<<<1, 128>>>(fW0, fb0, fW1, fb1, fW2, fb2, out);
}

// round 16
// speedup vs baseline: 1.0934x; 1.0045x over previous
#include <cuda_runtime.h>
#include <math.h>

#define NN 5000
#define NE 60000
#define NT 400000

// ---------------- scratch (device globals) --------------------------------------
__device__ float g_bondvec[NE * 3];
__device__ float g_dist[NE];
__device__ float g_rbf[NE * 9];
__device__ float g_cut3[NE];
__device__ float g_tbw[NT * 9];
__device__ int   g_endatom[NT];
__device__ float g_nodefeat[NN * 128];
__device__ float g_edgefeat[NE * 128];
__device__ float g_atoms[NN * 9];
__device__ float g_nb[NE * 9];
__device__ float g_nodepre[8 * NN * 128];   // slices: br*4 + chain*2 + side
__device__ float g_mean[128];
__device__ unsigned g_wbf16[6 * 6 * 128 * 64];  // [kbr][layer:{h0e,h1,h2,g0e,g1,g2}][128][64w]

struct Scales { float v[9]; };

__constant__ float c_roots[9] = {
    3.141592653589793f, 6.283185307179586f, 9.42477796076938f,
    4.493409457909064f, 7.725251836937707f, 10.904121659428899f,
    5.763459196894550f, 9.095011330476355f, 12.322940970566582f};

#define Y00F 0.28209479177387814f
#define Y10F 0.4886025119029199f
#define Y20F 0.31539156525252005f

__device__ __forceinline__ float siluf(float v) { return v / (1.f + expf(-v)); }
__device__ __forceinline__ float sigf(float v)  { return 1.f / (1.f + expf(-v)); }

__device__ __forceinline__ float jlf(int l, float x) {
    float s, c;
    sincosf(x, &s, &c);
    float inv = 1.f / x;
    if (l == 0) return s * inv;
    if (l == 1) return (s * inv - c) * inv;
    return (3.f * inv * inv - 1.f) * s * inv - 3.f * c * inv * inv;
}

// ---------------- mma / pack primitives -----------------------------------------
__device__ __forceinline__ unsigned f2tf(float x) {
    unsigned u;
    asm("cvt.rna.tf32.f32 %0, %1;" : "=r"(u) : "f"(x));
    return u;
}
__device__ __forceinline__ void mma_tf32(float* d, const unsigned* a, unsigned b0, unsigned b1) {
    asm volatile(
        "mma.sync.aligned.m16n8k8.row.col.f32.tf32.tf32.f32 "
        "{%0,%1,%2,%3}, {%4,%5,%6,%7}, {%8,%9}, {%0,%1,%2,%3};"
        : "+f"(d[0]), "+f"(d[1]), "+f"(d[2]), "+f"(d[3])
        : "r"(a[0]), "r"(a[1]), "r"(a[2]), "r"(a[3]), "r"(b0), "r"(b1));
}
__device__ __forceinline__ unsigned pack_bf16(float lo, float hi) {
    unsigned r;
    asm("cvt.rn.bf16x2.f32 %0, %1, %2;" : "=r"(r) : "f"(hi), "f"(lo));
    return r;
}
__device__ __forceinline__ float bf_lo(unsigned p) { return __uint_as_float(p << 16); }
__device__ __forceinline__ float bf_hi(unsigned p) { return __uint_as_float(p & 0xffff0000u); }
__device__ __forceinline__ void ldm_x4(unsigned& r0, unsigned& r1, unsigned& r2, unsigned& r3,
                                       unsigned addr) {
    asm volatile("ldmatrix.sync.aligned.m8n8.x4.shared.b16 {%0,%1,%2,%3}, [%4];"
                 : "=r"(r0), "=r"(r1), "=r"(r2), "=r"(r3) : "r"(addr));
}
__device__ __forceinline__ void ldm_x4_t(unsigned& r0, unsigned& r1, unsigned& r2, unsigned& r3,
                                         unsigned addr) {
    asm volatile("ldmatrix.sync.aligned.m8n8.x4.trans.shared.b16 {%0,%1,%2,%3}, [%4];"
                 : "=r"(r0), "=r"(r1), "=r"(r2), "=r"(r3) : "r"(addr));
}
__device__ __forceinline__ void mma_bf16(float* d, const unsigned* a, unsigned b0, unsigned b1) {
    asm volatile(
        "mma.sync.aligned.m16n8k16.row.col.f32.bf16.bf16.f32 "
        "{%0,%1,%2,%3}, {%4,%5,%6,%7}, {%8,%9}, {%0,%1,%2,%3};"
        : "+f"(d[0]), "+f"(d[1]), "+f"(d[2]), "+f"(d[3])
        : "r"(a[0]), "r"(a[1]), "r"(a[2]), "r"(a[3]), "r"(b0), "r"(b1));
}

// ---------------- kernel 0: geom + nodeinit + zero mean + weight conv -----------
#define CONVW_N (6 * 6 * 8192)
__global__ void k_setup0(const float* __restrict__ pos, const int* __restrict__ src,
                         const int* __restrict__ dst, const int* __restrict__ node_type,
                         const float* __restrict__ emb, Scales sc,
                         const float* __restrict__ W0, const float* __restrict__ W1,
                         const float* __restrict__ W2, const float* __restrict__ gW0,
                         const float* __restrict__ gW1, const float* __restrict__ gW2) {
    int idx = blockIdx.x * blockDim.x + threadIdx.x;
    if (idx < NE) {
        int e = idx;
        int s = src[e], d = dst[e];
        float dx = pos[d * 3 + 0] - pos[s * 3 + 0];
        float dy = pos[d * 3 + 1] - pos[s * 3 + 1];
        float dz = pos[d * 3 + 2] - pos[s * 3 + 2];
        float dist = sqrtf(dx * dx + dy * dy + dz * dz + 1e-12f);
        g_bondvec[e * 3 + 0] = dx;
        g_bondvec[e * 3 + 1] = dy;
        g_bondvec[e * 3 + 2] = dz;
        g_dist[e] = dist;
#pragma unroll
        for (int l = 0; l < 3; l++)
#pragma unroll
            for (int n = 0; n < 3; n++)
                g_rbf[e * 9 + l * 3 + n] = jlf(l, dist * c_roots[l * 3 + n] * 0.2f) * sc.v[l * 3 + n];
        float xx = dist * 0.25f;
        float x2 = xx * xx, x3 = x2 * xx;
        g_cut3[e] = 1.f - 6.f * x3 * x2 + 15.f * x2 * x2 - 10.f * x3;
    } else if (idx < NE + NN * 128) {
        int i = idx - NE;
        int n = i >> 7, c = i & 127;
        g_nodefeat[i] = emb[node_type[n] * 128 + c];
    } else if (idx < NE + NN * 128 + 128) {
        g_mean[idx - NE - NN * 128] = 0.f;
    } else if (idx < NE + NN * 128 + 128 + CONVW_N) {
        int w = idx - (NE + NN * 128 + 128);
        int kbr = w / 49152;
        int rem = w - kbr * 49152;
        int l = rem / 8192;
        int pos_ = rem - l * 8192;
        int row = pos_ >> 6, cw = pos_ & 63;
        const float* srcw;
        if (l == 0)      srcw = W0  + (size_t)kbr * 384 * 128 + 256 * 128;
        else if (l == 1) srcw = W1  + (size_t)kbr * 128 * 128;
        else if (l == 2) srcw = W2  + (size_t)kbr * 128 * 128;
        else if (l == 3) srcw = gW0 + (size_t)kbr * 384 * 128 + 256 * 128;
        else if (l == 4) srcw = gW1 + (size_t)kbr * 128 * 128;
        else             srcw = gW2 + (size_t)kbr * 128 * 128;
        float2 v = *(const float2*)(srcw + row * 128 + cw * 2);
        g_wbf16[w] = pack_bf16(v.x, v.y);
    }
}

// ---------------- kernel 1: triplet (+fused k=0 scatter) + edgeemb --------------
// g_nb must be zeroed and g_atoms (k=0) computed BEFORE this kernel (k_block_setup).
__global__ void k_setup1(const int* __restrict__ t_src, const int* __restrict__ t_dst,
                         const int* __restrict__ dst,
                         const float* __restrict__ W, const float* __restrict__ b) {
    int idx = blockIdx.x * blockDim.x + threadIdx.x;
    if (idx < NT) {
        int t = idx;
        int es = t_src[t], ed = t_dst[t];
        float v1x = g_bondvec[es * 3 + 0], v1y = g_bondvec[es * 3 + 1], v1z = g_bondvec[es * 3 + 2];
        float v2x = g_bondvec[ed * 3 + 0], v2y = g_bondvec[ed * 3 + 1], v2z = g_bondvec[ed * 3 + 2];
        float cost = (v1x * v2x + v1y * v2y + v1z * v2z) / (g_dist[es] * g_dist[ed]);
        float shf[3];
        shf[0] = Y00F;
        shf[1] = Y10F * cost;
        shf[2] = Y20F * (3.f * cost * cost - 1.f);
        float tw = g_cut3[es] * g_cut3[ed];
        int ea = dst[ed];
        g_endatom[t] = ea;
        float tb[9];
#pragma unroll
        for (int l = 0; l < 3; l++)
#pragma unroll
            for (int n = 0; n < 3; n++)
                tb[l * 3 + n] = g_rbf[ed * 9 + l * 3 + n] * shf[l] * tw;
#pragma unroll
        for (int q = 0; q < 9; q++) {
            g_tbw[t * 9 + q] = tb[q];
            atomicAdd(&g_nb[es * 9 + q], tb[q] * g_atoms[ea * 9 + q]);  // k=0 tripacc fused
        }
    } else if (idx < NT + NE * 128) {
        int i = idx - NT;
        int e = i >> 7, j = i & 127;
        float acc = b[j];
#pragma unroll
        for (int q = 0; q < 9; q++) acc = fmaf(g_rbf[e * 9 + q], W[q * 128 + j], acc);
        g_edgefeat[i] = siluf(acc);
    }
}

// ---------------- kernel 2: nodegemm(8 slices, tf32) + atoms + zero_nb ----------
#define NG_BLOCKS 320
#define AT_BLOCKS 176
#define ZB_BLOCKS 2110

__global__ void __launch_bounds__(256) k_block_setup(
    const float* __restrict__ W0, const float* __restrict__ gW0,
    const float* __restrict__ b0, const float* __restrict__ gb0,
    const float* __restrict__ taW, const float* __restrict__ tab, int k) {
    int blk = blockIdx.x;
    if (blk < NG_BLOCKS) {
        __shared__ unsigned sA[128 * 40];
        __shared__ unsigned sB[32 * 136];
        int slice = blk & 7, mt = blk >> 3;
        int br = slice >> 2, chain = (slice >> 1) & 1, side = slice & 1;
        const float* Wbase = (chain ? gW0 : W0) + (size_t)(k * 2 + br) * 384 * 128 + side * 128 * 128;
        const float* bias = side == 0 ? ((chain ? gb0 : b0) + (k * 2 + br) * 128) : nullptr;
        float* out = g_nodepre + (size_t)slice * NN * 128;
        const float* A = g_nodefeat;
        int bm = mt * 128;

        const int tid = threadIdx.x;
        const int lane = tid & 31, wid = tid >> 5;
        const int wm = (wid & 3) * 32, wn = (wid >> 2) * 64;
        float acc[2][8][4];
#pragma unroll
        for (int i = 0; i < 2; i++)
#pragma unroll
            for (int j = 0; j < 8; j++)
#pragma unroll
                for (int q = 0; q < 4; q++) acc[i][j][q] = 0.f;

        const int r0 = tid >> 3, c4 = tid & 7;
        const int bk0 = tid >> 5, bn4 = tid & 31;
        for (int kt = 0; kt < 4; kt++) {
#pragma unroll
            for (int i = 0; i < 4; i++) {
                int gm = bm + r0 + 32 * i;
                float4 v = make_float4(0.f, 0.f, 0.f, 0.f);
                if (gm < NN) v = *(const float4*)(A + (size_t)gm * 128 + kt * 32 + c4 * 4);
                uint4 u;
                u.x = f2tf(v.x); u.y = f2tf(v.y); u.z = f2tf(v.z); u.w = f2tf(v.w);
                *(uint4*)&sA[(r0 + 32 * i) * 40 + c4 * 4] = u;
            }
#pragma unroll
            for (int i = 0; i < 4; i++) {
                float4 v = *(const float4*)(Wbase + (size_t)(kt * 32 + bk0 + 8 * i) * 128 + bn4 * 4);
                uint4 u;
                u.x = f2tf(v.x); u.y = f2tf(v.y); u.z = f2tf(v.z); u.w = f2tf(v.w);
                *(uint4*)&sB[(bk0 + 8 * i) * 136 + bn4 * 4] = u;
            }
            __syncthreads();
#pragma unroll
            for (int ks = 0; ks < 4; ks++) {
                unsigned a[2][4];
                int arow = wm + (lane >> 2);
                int acol = ks * 8 + (lane & 3);
#pragma unroll
                for (int m2 = 0; m2 < 2; m2++) {
                    int rr = arow + m2 * 16;
                    a[m2][0] = sA[rr * 40 + acol];
                    a[m2][1] = sA[(rr + 8) * 40 + acol];
                    a[m2][2] = sA[rr * 40 + acol + 4];
                    a[m2][3] = sA[(rr + 8) * 40 + acol + 4];
                }
                int bro = (ks * 8 + (lane & 3)) * 136 + wn + (lane >> 2);
#pragma unroll
                for (int nt = 0; nt < 8; nt++) {
                    unsigned b0r = sB[bro + nt * 8];
                    unsigned b1r = sB[bro + 4 * 136 + nt * 8];
                    mma_tf32(acc[0][nt], a[0], b0r, b1r);
                    mma_tf32(acc[1][nt], a[1], b0r, b1r);
                }
            }
            __syncthreads();
        }
#pragma unroll
        for (int m2 = 0; m2 < 2; m2++) {
#pragma unroll
            for (int nt = 0; nt < 8; nt++) {
                int gn = wn + nt * 8 + 2 * (lane & 3);
                float bv0 = bias ? bias[gn] : 0.f;
                float bv1 = bias ? bias[gn + 1] : 0.f;
                int gm0 = bm + wm + m2 * 16 + (lane >> 2);
                if (gm0 < NN)
                    *(float2*)(out + (size_t)gm0 * 128 + gn) =
                        make_float2(acc[m2][nt][0] + bv0, acc[m2][nt][1] + bv1);
                int gm1 = gm0 + 8;
                if (gm1 < NN)
                    *(float2*)(out + (size_t)gm1 * 128 + gn) =
                        make_float2(acc[m2][nt][2] + bv0, acc[m2][nt][3] + bv1);
            }
        }
    } else if (blk < NG_BLOCKS + AT_BLOCKS) {
        int idx = (blk - NG_BLOCKS) * 256 + threadIdx.x;
        if (idx < NN * 9) {
            int n = idx / 9, j = idx % 9;
            float acc = tab[k * 9 + j];
            const float* nf = &g_nodefeat[n * 128];
            const float* W = taW + (size_t)k * 128 * 9;
#pragma unroll 8
            for (int i = 0; i < 128; i++) acc = fmaf(nf[i], W[i * 9 + j], acc);
            g_atoms[idx] = sigf(acc);
        }
    } else {
        int idx = (blk - NG_BLOCKS - AT_BLOCKS) * 256 + threadIdx.x;
        if (idx < NE * 9) g_nb[idx] = 0.f;
    }
}

// ---------------- tripacc (k=1,2 only; k=0 fused into setup1) -------------------
__global__ void k_tripacc(const int* __restrict__ t_src) {
    int t = blockIdx.x * blockDim.x + threadIdx.x;
    if (t >= NT) return;
    int es = t_src[t];
    int ea = g_endatom[t];
#pragma unroll
    for (int q = 0; q < 9; q++)
        atomicAdd(&g_nb[es * 9 + q], g_tbw[t * 9 + q] * g_atoms[ea * 9 + q]);
}

// ---------------- fused megakernel: tb-update + both branches (BM=64) -----------
// smem bytes: sAct @0 (17408) | sAe @17408 (17408) | sB0 @34816 (17408) |
//             sB1 @52224 (17408) | swt @69632 (4608)  => 74240  (3 CTAs/SM)
#define FUSED_SMEM 74240
#define FUSED_GRID ((NE + 63) / 64)
#define STR 136

__global__ void __launch_bounds__(256, 3) fused_block(
    const int* __restrict__ src, const int* __restrict__ dst,
    const float* __restrict__ Wbk, const float* __restrict__ Wgk,
    const unsigned* __restrict__ wbase,                 // bf16 weights, this k (2 branches)
    const float* __restrict__ b1k, const float* __restrict__ b2k,
    const float* __restrict__ gb1k, const float* __restrict__ gb2k,
    const float* __restrict__ wtk) {
    extern __shared__ char smem_raw[];
    unsigned* sActw = (unsigned*)(smem_raw);
    unsigned* sAew  = (unsigned*)(smem_raw + 17408);
    float*    swt   = (float*)(smem_raw + 69632);

    const unsigned act_u = (unsigned)__cvta_generic_to_shared(sActw);
    const unsigned ae_u  = (unsigned)__cvta_generic_to_shared(sAew);
    const unsigned b0_u  = (unsigned)__cvta_generic_to_shared(smem_raw + 34816);
    const unsigned b1_u  = (unsigned)__cvta_generic_to_shared(smem_raw + 52224);

    const int tid = threadIdx.x;
    const int lane = tid & 31, wid = tid >> 5;
    const int wm = (wid & 3) * 16, wn = (wid >> 2) * 64;
    const int bm = blockIdx.x * 64;

    const int rr0 = wm + (lane >> 2);
    const int e0 = bm + rr0, e1 = e0 + 8;
    const bool v0 = e0 < NE, v1 = e1 < NE;
    const int s0 = v0 ? src[e0] : 0, d0 = v0 ? dst[e0] : 0;
    const int s1 = v1 ? src[e1] : 0, d1 = v1 ? dst[e1] : 0;

    // ---- stage A: three-body edge update -> g_edgefeat (fp32) + sAe (bf16) -----
    {
        float* sWb = (float*)sActw;                    // scratch (9x128)
        float* sWg = (float*)(smem_raw + 34816);       // scratch in sB0 region
        for (int i = tid; i < 9 * 128; i += 256) { sWb[i] = Wbk[i]; sWg[i] = Wgk[i]; }
        __syncthreads();
        for (int i = tid; i < 64 * 64; i += 256) {
            int row = i >> 6, cp = i & 63;
            int e = bm + row;
            float nv0 = 0.f, nv1 = 0.f;
            if (e < NE) {
                int c0 = 2 * cp;
                float s10 = 0.f, s20 = 0.f, s11 = 0.f, s21 = 0.f;
#pragma unroll
                for (int q = 0; q < 9; q++) {
                    float nv = g_nb[e * 9 + q];
                    s10 = fmaf(nv, sWb[q * 128 + c0], s10);
                    s20 = fmaf(nv, sWg[q * 128 + c0], s20);
                    s11 = fmaf(nv, sWb[q * 128 + c0 + 1], s11);
                    s21 = fmaf(nv, sWg[q * 128 + c0 + 1], s21);
                }
                float2 ef = *(const float2*)(g_edgefeat + (size_t)e * 128 + c0);
                nv0 = ef.x + siluf(s10) * sigf(s20);
                nv1 = ef.y + siluf(s11) * sigf(s21);
                *(float2*)(g_edgefeat + (size_t)e * 128 + c0) = make_float2(nv0, nv1);
            }
            sAew[row * 68 + cp] = pack_bf16(nv0, nv1);
        }
        __syncthreads();   // sWb/sWg reads done before sB0 reuse; sAe visible
    }

    float acc[8][4];
    unsigned hpk[8][2];   // silu(h2) packed bf16x2

    auto zero_acc = [&] {
#pragma unroll
        for (int j = 0; j < 8; j++)
#pragma unroll
            for (int q = 0; q < 4; q++) acc[j][q] = 0.f;
    };
    // async-copy one 64x128 bf16 weight slab (row stride 272B in smem)
    auto cp_slab = [&](const unsigned* Wb, int slab, unsigned bufu) {
#pragma unroll
        for (int i = 0; i < 4; i++) {
            int c = tid + 256 * i;
            int row = c >> 4, c4 = c & 15;
            unsigned dstb = bufu + (unsigned)(row * 272 + c4 * 16);
            const unsigned* srcp = Wb + (slab * 64 + row) * 64 + c4 * 4;
            asm volatile("cp.async.cg.shared.global [%0], [%1], 16;"
                         :: "r"(dstb), "l"(srcp) : "memory");
        }
        asm volatile("cp.async.commit_group;" ::: "memory");
    };
    auto compute_tile = [&](unsigned abase, unsigned bbase, int kbase) {
        unsigned a[4];
        {
            int arow = wm + (lane & 7) + ((lane >> 3) & 1) * 8;
            int acol = kbase + (lane >> 4) * 8;
            ldm_x4(a[0], a[1], a[2], a[3], abase + (unsigned)(arow * STR + acol) * 2);
        }
        int krow = (kbase & 63) + (lane & 15);
        int cofs = (lane >> 4) * 8;
#pragma unroll
        for (int j = 0; j < 4; j++) {
            unsigned b[4];
            int n0 = wn + 16 * j;
            ldm_x4_t(b[0], b[1], b[2], b[3], bbase + (unsigned)(krow * STR + n0 + cofs) * 2);
            mma_bf16(acc[2 * j], a, b[0], b[1]);
            mma_bf16(acc[2 * j + 1], a, b[2], b[3]);
        }
    };
    auto gemm_layer = [&](unsigned abase, const unsigned* Wb) {
        zero_acc();
        cp_slab(Wb, 0, b0_u);
        asm volatile("cp.async.wait_group 0;" ::: "memory");
        __syncthreads();
        cp_slab(Wb, 1, b1_u);
#pragma unroll
        for (int ks = 0; ks < 4; ks++) compute_tile(abase, b0_u, ks * 16);
        asm volatile("cp.async.wait_group 0;" ::: "memory");
        __syncthreads();
#pragma unroll
        for (int ks = 0; ks < 4; ks++) compute_tile(abase, b1_u, 64 + ks * 16);
        __syncthreads();
    };

    // one gated-MLP chain; leaves final raw L2 pre-activation in acc.
    auto run_chain = [&](const unsigned* wch, const float* NS, const float* ND,
                         const float* b1v) {
        gemm_layer(ae_u, wch);                      // L0 (A = edge tile)
#pragma unroll
        for (int nt = 0; nt < 8; nt++) {
            int gn = wn + nt * 8 + 2 * (lane & 3);
            float2 ns0 = v0 ? *(const float2*)(NS + (size_t)s0 * 128 + gn) : make_float2(0, 0);
            float2 nd0 = v0 ? *(const float2*)(ND + (size_t)d0 * 128 + gn) : make_float2(0, 0);
            float2 ns1 = v1 ? *(const float2*)(NS + (size_t)s1 * 128 + gn) : make_float2(0, 0);
            float2 nd1 = v1 ? *(const float2*)(ND + (size_t)d1 * 128 + gn) : make_float2(0, 0);
            sActw[rr0 * 68 + (gn >> 1)] =
                pack_bf16(siluf(acc[nt][0] + ns0.x + nd0.x), siluf(acc[nt][1] + ns0.y + nd0.y));
            sActw[(rr0 + 8) * 68 + (gn >> 1)] =
                pack_bf16(siluf(acc[nt][2] + ns1.x + nd1.x), siluf(acc[nt][3] + ns1.y + nd1.y));
        }
        gemm_layer(act_u, wch + 8192);              // L1
#pragma unroll
        for (int nt = 0; nt < 8; nt++) {
            int gn = wn + nt * 8 + 2 * (lane & 3);
            float bv0 = b1v[gn], bv1 = b1v[gn + 1];
            sActw[rr0 * 68 + (gn >> 1)] =
                pack_bf16(siluf(acc[nt][0] + bv0), siluf(acc[nt][1] + bv1));
            sActw[(rr0 + 8) * 68 + (gn >> 1)] =
                pack_bf16(siluf(acc[nt][2] + bv0), siluf(acc[nt][3] + bv1));
        }
        gemm_layer(act_u, wch + 16384);             // L2 -> raw acc
    };

    for (int br = 0; br < 2; br++) {
        const unsigned* wbr = wbase + (size_t)br * 49152;
        const float* bh1 = b1k + br * 128;
        const float* bg1 = gb1k + br * 128;
        const float* bh2 = b2k + br * 128;
        const float* bg2 = gb2k + br * 128;
        const float* NSh = g_nodepre + (size_t)(br * 4 + 0) * NN * 128;
        const float* NDh = g_nodepre + (size_t)(br * 4 + 1) * NN * 128;
        const float* NSg = g_nodepre + (size_t)(br * 4 + 2) * NN * 128;
        const float* NDg = g_nodepre + (size_t)(br * 4 + 3) * NN * 128;

        for (int i = tid; i < 9 * 128; i += 256) swt[i] = wtk[br * 9 * 128 + i];
        // ordering provided by first gemm_layer's internal barrier

        // h chain -> pack silu(h2) to bf16x2
        run_chain(wbr, NSh, NDh, bh1);
#pragma unroll
        for (int nt = 0; nt < 8; nt++) {
            int gn = wn + nt * 8 + 2 * (lane & 3);
            float bv0 = bh2[gn], bv1 = bh2[gn + 1];
            hpk[nt][0] = pack_bf16(siluf(acc[nt][0] + bv0), siluf(acc[nt][1] + bv1));
            hpk[nt][1] = pack_bf16(siluf(acc[nt][2] + bv0), siluf(acc[nt][3] + bv1));
        }
        // g chain (raw L2 in acc)
        run_chain(wbr + 24576, NSg, NDg, bg1);

        // ---- epilogue ----
        float rb0[9], rb1[9];
#pragma unroll
        for (int q = 0; q < 9; q++) {
            rb0[q] = v0 ? g_rbf[e0 * 9 + q] : 0.f;
            rb1[q] = v1 ? g_rbf[e1 * 9 + q] : 0.f;
        }
#pragma unroll
        for (int nt = 0; nt < 8; nt++) {
            int gn = wn + nt * 8 + 2 * (lane & 3);
            float w00 = 0.f, w01 = 0.f, w10 = 0.f, w11 = 0.f;
#pragma unroll
            for (int q = 0; q < 9; q++) {
                float wc0 = swt[q * 128 + gn], wc1 = swt[q * 128 + gn + 1];
                w00 = fmaf(rb0[q], wc0, w00);
                w01 = fmaf(rb0[q], wc1, w01);
                w10 = fmaf(rb1[q], wc0, w10);
                w11 = fmaf(rb1[q], wc1, w11);
            }
            float gb0v = bg2[gn], gb1v = bg2[gn + 1];
            float val0 = bf_lo(hpk[nt][0]) * sigf(acc[nt][0] + gb0v) * w00;
            float val1 = bf_hi(hpk[nt][0]) * sigf(acc[nt][1] + gb1v) * w01;
            float val2 = bf_lo(hpk[nt][1]) * sigf(acc[nt][2] + gb0v) * w10;
            float val3 = bf_hi(hpk[nt][1]) * sigf(acc[nt][3] + gb1v) * w11;
            if (br == 0) {
                if (v0) {
                    float2 base = *(const float2*)(g_edgefeat + (size_t)e0 * 128 + gn);
                    float n0v = base.x + val0, n1v = base.y + val1;
                    *(float2*)(g_edgefeat + (size_t)e0 * 128 + gn) = make_float2(n0v, n1v);
                    sAew[rr0 * 68 + (gn >> 1)] = pack_bf16(n0v, n1v);
                }
                if (v1) {
                    float2 base = *(const float2*)(g_edgefeat + (size_t)e1 * 128 + gn);
                    float n2v = base.x + val2, n3v = base.y + val3;
                    *(float2*)(g_edgefeat + (size_t)e1 * 128 + gn) = make_float2(n2v, n3v);
                    sAew[(rr0 + 8) * 68 + (gn >> 1)] = pack_bf16(n2v, n3v);
                }
            } else {
                if (v0) {
                    atomicAdd(&g_nodefeat[(size_t)d0 * 128 + gn], val0);
                    atomicAdd(&g_nodefeat[(size_t)d0 * 128 + gn + 1], val1);
                }
                if (v1) {
                    atomicAdd(&g_nodefeat[(size_t)d1 * 128 + gn], val2);
                    atomicAdd(&g_nodefeat[(size_t)d1 * 128 + gn + 1], val3);
                }
            }
        }
        __syncthreads();   // sAe update visible before br=1 L0 reads it
    }
}

// ---------------- readout -------------------------------------------------------
__global__ void k_mean() {
    int j = threadIdx.x;
    int b = blockIdx.x;
    float s = 0.f;
    for (int n = b * 125; n < b * 125 + 125; n++) s += g_nodefeat[n * 128 + j];
    atomicAdd(&g_mean[j], s);
}

__global__ void k_final(const float* __restrict__ fW0, const float* __restrict__ fb0,
                        const float* __restrict__ fW1, const float* __restrict__ fb1,
                        const float* __restrict__ fW2, const float* __restrict__ fb2,
                        float* __restrict__ out) {
    __shared__ float v[128], h0[128], h1[128], red[128];
    int j = threadIdx.x;
    v[j] = g_mean[j] / (float)NN;
    __syncthreads();
    float a = fb0[j];
    for (int i = 0; i < 128; i++) a = fmaf(v[i], fW0[i * 128 + j], a);
    h0[j] = siluf(a);
    __syncthreads();
    a = fb1[j];
    for (int i = 0; i < 128; i++) a = fmaf(h0[i], fW1[i * 128 + j], a);
    h1[j] = siluf(a);
    __syncthreads();
    red[j] = h1[j] * fW2[j];
    __syncthreads();
    for (int st = 64; st > 0; st >>= 1) {
        if (j < st) red[j] += red[j + st];
        __syncthreads();
    }
    if (j == 0) out[0] = red[0] + fb2[0];
}

// ---------------- host ----------------------------------------------------------
static double h_jl(int l, double x) {
    double s = sin(x), c = cos(x);
    if (l == 1) return s / (x * x) - c / x;
    if (l == 2) return (3.0 / (x * x * x) - 1.0 / x) * s - 3.0 * c / (x * x);
    return (15.0 / (x * x * x * x) - 6.0 / (x * x)) * s - (15.0 / (x * x * x) - 1.0 / x) * c;
}

extern "C" void kernel_launch(void* const* d_in, const int* in_sizes, int n_in,
                              void* d_out, int out_size) {
    const float* pos  = (const float*)d_in[0];
    const int* node_type = (const int*)d_in[1];
    const int* src  = (const int*)d_in[2];
    const int* dst  = (const int*)d_in[3];
    const int* t_src = (const int*)d_in[4];
    const int* t_dst = (const int*)d_in[5];
    const float* emb  = (const float*)d_in[6];
    const float* eW   = (const float*)d_in[7];
    const float* eb   = (const float*)d_in[8];
    const float* taW  = (const float*)d_in[9];
    const float* tab  = (const float*)d_in[10];
    const float* tbW  = (const float*)d_in[11];
    const float* tbWg = (const float*)d_in[12];
    const float* W0 = (const float*)d_in[13];  const float* b0 = (const float*)d_in[14];
    const float* W1 = (const float*)d_in[15];  const float* b1 = (const float*)d_in[16];
    const float* W2 = (const float*)d_in[17];  const float* b2 = (const float*)d_in[18];
    const float* gW0 = (const float*)d_in[19]; const float* gb0 = (const float*)d_in[20];
    const float* gW1 = (const float*)d_in[21]; const float* gb1 = (const float*)d_in[22];
    const float* gW2 = (const float*)d_in[23]; const float* gb2 = (const float*)d_in[24];
    const float* wt = (const float*)d_in[25];
    const float* fW0 = (const float*)d_in[26]; const float* fb0 = (const float*)d_in[27];
    const float* fW1 = (const float*)d_in[28]; const float* fb1 = (const float*)d_in[29];
    const float* fW2 = (const float*)d_in[30]; const float* fb2 = (const float*)d_in[31];
    float* out = (float*)d_out;

    Scales sc;
    {
        const double roots[9] = {
            3.141592653589793, 6.283185307179586, 9.42477796076938,
            4.493409457909064, 7.725251836937707, 10.904121659428899,
            5.763459196894550, 9.095011330476355, 12.322940970566582};
        double fac = sqrt(2.0 / 125.0);
        for (int l = 0; l < 3; l++)
            for (int n = 0; n < 3; n++)
                sc.v[l * 3 + n] = (float)(fac / fabs(h_jl(l + 1, roots[l * 3 + n])));
    }

    unsigned* pwb;
    cudaGetSymbolAddress((void**)&pwb, g_wbf16);

    cudaFuncSetAttribute(fused_block, cudaFuncAttributeMaxDynamicSharedMemorySize, FUSED_SMEM);

    int n0 = NE + NN * 128 + 128 + CONVW_N;
    k_setup0<<<(n0 + 255) / 256, 256>>>(pos, src, dst, node_type, emb, sc,
                                        W0, W1, W2, gW0, gW1, gW2);
    k_block_setup<<<NG_BLOCKS + AT_BLOCKS + ZB_BLOCKS, 256>>>(W0, gW0, b0, gb0, taW, tab, 0);
    int n1 = NT + NE * 128;
    k_setup1<<<(n1 + 255) / 256, 256>>>(t_src, t_dst, dst, eW, eb);  // includes k=0 tripacc

    for (int k = 0; k < 3; k++) {
        if (k > 0) {
            k_block_setup<<<NG_BLOCKS + AT_BLOCKS + ZB_BLOCKS, 256>>>(W0, gW0, b0, gb0, taW, tab, k);
            k_tripacc<<<(NT + 255) / 256, 256>>>(t_src);
        }
        fused_block<<<FUSED_GRID, 256, FUSED_SMEM>>>(
            src, dst, tbW + k * 9 * 128, tbWg + k * 9 * 128,
            pwb + (size_t)k * 2 * 49152,
            b1 + k * 2 * 128, b2 + k * 2 * 128,
            gb1 + k * 2 * 128, gb2 + k * 2 * 128,
            wt + k * 2 * 9 * 128);
    }
    k_mean<<<40, 128>>>();
    k_final<<<1, 128>>>(fW0, fb0, fW1, fb1, fW2, fb2, out);
}

// round 17
// speedup vs baseline: 1.2976x; 1.1867x over previous
#include <cuda_runtime.h>
#include <math.h>

#define NN 5000
#define NE 60000
#define NT 400000

// ---------------- scratch (device globals) --------------------------------------
__device__ float g_bondvec[NE * 3];
__device__ float g_dist[NE];
__device__ float g_rbf[NE * 9];
__device__ float g_cut3[NE];
__device__ float g_tbw[NT * 9];
__device__ int   g_endatom[NT];
__device__ float g_nodefeat[NN * 128];
__device__ float g_edgefeat[NE * 128];
__device__ float g_atoms[NN * 9];
__device__ float g_nb[NE * 9];
__device__ float g_nodepre[8 * NN * 128];   // slices: br*4 + chain*2 + side
__device__ float g_mean[128];
__device__ unsigned g_wbf16[6 * 6 * 128 * 64];  // [kbr][layer:{h0e,h1,h2,g0e,g1,g2}][128][64w]

struct Scales { float v[9]; };

__constant__ float c_roots[9] = {
    3.141592653589793f, 6.283185307179586f, 9.42477796076938f,
    4.493409457909064f, 7.725251836937707f, 10.904121659428899f,
    5.763459196894550f, 9.095011330476355f, 12.322940970566582f};

#define Y00F 0.28209479177387814f
#define Y10F 0.4886025119029199f
#define Y20F 0.31539156525252005f

__device__ __forceinline__ float siluf(float v) { return v / (1.f + expf(-v)); }
__device__ __forceinline__ float sigf(float v)  { return 1.f / (1.f + expf(-v)); }

__device__ __forceinline__ float jlf(int l, float x) {
    float s, c;
    sincosf(x, &s, &c);
    float inv = 1.f / x;
    if (l == 0) return s * inv;
    if (l == 1) return (s * inv - c) * inv;
    return (3.f * inv * inv - 1.f) * s * inv - 3.f * c * inv * inv;
}

// ---------------- mma / pack primitives -----------------------------------------
__device__ __forceinline__ unsigned f2tf(float x) {
    unsigned u;
    asm("cvt.rna.tf32.f32 %0, %1;" : "=r"(u) : "f"(x));
    return u;
}
__device__ __forceinline__ void mma_tf32(float* d, const unsigned* a, unsigned b0, unsigned b1) {
    asm volatile(
        "mma.sync.aligned.m16n8k8.row.col.f32.tf32.tf32.f32 "
        "{%0,%1,%2,%3}, {%4,%5,%6,%7}, {%8,%9}, {%0,%1,%2,%3};"
        : "+f"(d[0]), "+f"(d[1]), "+f"(d[2]), "+f"(d[3])
        : "r"(a[0]), "r"(a[1]), "r"(a[2]), "r"(a[3]), "r"(b0), "r"(b1));
}
__device__ __forceinline__ unsigned pack_bf16(float lo, float hi) {
    unsigned r;
    asm("cvt.rn.bf16x2.f32 %0, %1, %2;" : "=r"(r) : "f"(hi), "f"(lo));
    return r;
}
__device__ __forceinline__ float bf_lo(unsigned p) { return __uint_as_float(p << 16); }
__device__ __forceinline__ float bf_hi(unsigned p) { return __uint_as_float(p & 0xffff0000u); }
__device__ __forceinline__ void ldm_x4(unsigned& r0, unsigned& r1, unsigned& r2, unsigned& r3,
                                       unsigned addr) {
    asm volatile("ldmatrix.sync.aligned.m8n8.x4.shared.b16 {%0,%1,%2,%3}, [%4];"
                 : "=r"(r0), "=r"(r1), "=r"(r2), "=r"(r3) : "r"(addr));
}
__device__ __forceinline__ void ldm_x4_t(unsigned& r0, unsigned& r1, unsigned& r2, unsigned& r3,
                                         unsigned addr) {
    asm volatile("ldmatrix.sync.aligned.m8n8.x4.trans.shared.b16 {%0,%1,%2,%3}, [%4];"
                 : "=r"(r0), "=r"(r1), "=r"(r2), "=r"(r3) : "r"(addr));
}
__device__ __forceinline__ void mma_bf16(float* d, const unsigned* a, unsigned b0, unsigned b1) {
    asm volatile(
        "mma.sync.aligned.m16n8k16.row.col.f32.bf16.bf16.f32 "
        "{%0,%1,%2,%3}, {%4,%5,%6,%7}, {%8,%9}, {%0,%1,%2,%3};"
        : "+f"(d[0]), "+f"(d[1]), "+f"(d[2]), "+f"(d[3])
        : "r"(a[0]), "r"(a[1]), "r"(a[2]), "r"(a[3]), "r"(b0), "r"(b1));
}

// ---------------- kernel 0: geom + nodeinit + zero mean + weight conv -----------
#define CONVW_N (6 * 6 * 8192)
__global__ void k_setup0(const float* __restrict__ pos, const int* __restrict__ src,
                         const int* __restrict__ dst, const int* __restrict__ node_type,
                         const float* __restrict__ emb, Scales sc,
                         const float* __restrict__ W0, const float* __restrict__ W1,
                         const float* __restrict__ W2, const float* __restrict__ gW0,
                         const float* __restrict__ gW1, const float* __restrict__ gW2) {
    int idx = blockIdx.x * blockDim.x + threadIdx.x;
    if (idx < NE) {
        int e = idx;
        int s = src[e], d = dst[e];
        float dx = pos[d * 3 + 0] - pos[s * 3 + 0];
        float dy = pos[d * 3 + 1] - pos[s * 3 + 1];
        float dz = pos[d * 3 + 2] - pos[s * 3 + 2];
        float dist = sqrtf(dx * dx + dy * dy + dz * dz + 1e-12f);
        g_bondvec[e * 3 + 0] = dx;
        g_bondvec[e * 3 + 1] = dy;
        g_bondvec[e * 3 + 2] = dz;
        g_dist[e] = dist;
#pragma unroll
        for (int l = 0; l < 3; l++)
#pragma unroll
            for (int n = 0; n < 3; n++)
                g_rbf[e * 9 + l * 3 + n] = jlf(l, dist * c_roots[l * 3 + n] * 0.2f) * sc.v[l * 3 + n];
        float xx = dist * 0.25f;
        float x2 = xx * xx, x3 = x2 * xx;
        g_cut3[e] = 1.f - 6.f * x3 * x2 + 15.f * x2 * x2 - 10.f * x3;
    } else if (idx < NE + NN * 128) {
        int i = idx - NE;
        int n = i >> 7, c = i & 127;
        g_nodefeat[i] = emb[node_type[n] * 128 + c];
    } else if (idx < NE + NN * 128 + 128) {
        g_mean[idx - NE - NN * 128] = 0.f;
    } else if (idx < NE + NN * 128 + 128 + CONVW_N) {
        int w = idx - (NE + NN * 128 + 128);
        int kbr = w / 49152;
        int rem = w - kbr * 49152;
        int l = rem / 8192;
        int pos_ = rem - l * 8192;
        int row = pos_ >> 6, cw = pos_ & 63;
        const float* srcw;
        if (l == 0)      srcw = W0  + (size_t)kbr * 384 * 128 + 256 * 128;
        else if (l == 1) srcw = W1  + (size_t)kbr * 128 * 128;
        else if (l == 2) srcw = W2  + (size_t)kbr * 128 * 128;
        else if (l == 3) srcw = gW0 + (size_t)kbr * 384 * 128 + 256 * 128;
        else if (l == 4) srcw = gW1 + (size_t)kbr * 128 * 128;
        else             srcw = gW2 + (size_t)kbr * 128 * 128;
        float2 v = *(const float2*)(srcw + row * 128 + cw * 2);
        g_wbf16[w] = pack_bf16(v.x, v.y);
    }
}

// ---------------- kernel 1: triplet (+fused k=0 scatter) + edgeemb --------------
__global__ void k_setup1(const int* __restrict__ t_src, const int* __restrict__ t_dst,
                         const int* __restrict__ dst,
                         const float* __restrict__ W, const float* __restrict__ b) {
    int idx = blockIdx.x * blockDim.x + threadIdx.x;
    if (idx < NT) {
        int t = idx;
        int es = t_src[t], ed = t_dst[t];
        float v1x = g_bondvec[es * 3 + 0], v1y = g_bondvec[es * 3 + 1], v1z = g_bondvec[es * 3 + 2];
        float v2x = g_bondvec[ed * 3 + 0], v2y = g_bondvec[ed * 3 + 1], v2z = g_bondvec[ed * 3 + 2];
        float cost = (v1x * v2x + v1y * v2y + v1z * v2z) / (g_dist[es] * g_dist[ed]);
        float shf[3];
        shf[0] = Y00F;
        shf[1] = Y10F * cost;
        shf[2] = Y20F * (3.f * cost * cost - 1.f);
        float tw = g_cut3[es] * g_cut3[ed];
        int ea = dst[ed];
        g_endatom[t] = ea;
        float tb[9];
#pragma unroll
        for (int l = 0; l < 3; l++)
#pragma unroll
            for (int n = 0; n < 3; n++)
                tb[l * 3 + n] = g_rbf[ed * 9 + l * 3 + n] * shf[l] * tw;
#pragma unroll
        for (int q = 0; q < 9; q++) {
            g_tbw[t * 9 + q] = tb[q];
            atomicAdd(&g_nb[es * 9 + q], tb[q] * g_atoms[ea * 9 + q]);  // k=0 tripacc fused
        }
    } else if (idx < NT + NE * 128) {
        int i = idx - NT;
        int e = i >> 7, j = i & 127;
        float acc = b[j];
#pragma unroll
        for (int q = 0; q < 9; q++) acc = fmaf(g_rbf[e * 9 + q], W[q * 128 + j], acc);
        g_edgefeat[i] = siluf(acc);
    }
}

// ---------------- kernel 2: nodegemm(8 slices, tf32) + atoms + zero_nb ----------
#define NG_BLOCKS 320
#define AT_BLOCKS 176
#define ZB_BLOCKS 2110

__global__ void __launch_bounds__(256) k_block_setup(
    const float* __restrict__ W0, const float* __restrict__ gW0,
    const float* __restrict__ b0, const float* __restrict__ gb0,
    const float* __restrict__ taW, const float* __restrict__ tab, int k) {
    int blk = blockIdx.x;
    if (blk < NG_BLOCKS) {
        __shared__ unsigned sA[128 * 40];
        __shared__ unsigned sB[32 * 136];
        int slice = blk & 7, mt = blk >> 3;
        int br = slice >> 2, chain = (slice >> 1) & 1, side = slice & 1;
        const float* Wbase = (chain ? gW0 : W0) + (size_t)(k * 2 + br) * 384 * 128 + side * 128 * 128;
        const float* bias = side == 0 ? ((chain ? gb0 : b0) + (k * 2 + br) * 128) : nullptr;
        float* out = g_nodepre + (size_t)slice * NN * 128;
        const float* A = g_nodefeat;
        int bm = mt * 128;

        const int tid = threadIdx.x;
        const int lane = tid & 31, wid = tid >> 5;
        const int wm = (wid & 3) * 32, wn = (wid >> 2) * 64;
        float acc[2][8][4];
#pragma unroll
        for (int i = 0; i < 2; i++)
#pragma unroll
            for (int j = 0; j < 8; j++)
#pragma unroll
                for (int q = 0; q < 4; q++) acc[i][j][q] = 0.f;

        const int r0 = tid >> 3, c4 = tid & 7;
        const int bk0 = tid >> 5, bn4 = tid & 31;
        for (int kt = 0; kt < 4; kt++) {
#pragma unroll
            for (int i = 0; i < 4; i++) {
                int gm = bm + r0 + 32 * i;
                float4 v = make_float4(0.f, 0.f, 0.f, 0.f);
                if (gm < NN) v = *(const float4*)(A + (size_t)gm * 128 + kt * 32 + c4 * 4);
                uint4 u;
                u.x = f2tf(v.x); u.y = f2tf(v.y); u.z = f2tf(v.z); u.w = f2tf(v.w);
                *(uint4*)&sA[(r0 + 32 * i) * 40 + c4 * 4] = u;
            }
#pragma unroll
            for (int i = 0; i < 4; i++) {
                float4 v = *(const float4*)(Wbase + (size_t)(kt * 32 + bk0 + 8 * i) * 128 + bn4 * 4);
                uint4 u;
                u.x = f2tf(v.x); u.y = f2tf(v.y); u.z = f2tf(v.z); u.w = f2tf(v.w);
                *(uint4*)&sB[(bk0 + 8 * i) * 136 + bn4 * 4] = u;
            }
            __syncthreads();
#pragma unroll
            for (int ks = 0; ks < 4; ks++) {
                unsigned a[2][4];
                int arow = wm + (lane >> 2);
                int acol = ks * 8 + (lane & 3);
#pragma unroll
                for (int m2 = 0; m2 < 2; m2++) {
                    int rr = arow + m2 * 16;
                    a[m2][0] = sA[rr * 40 + acol];
                    a[m2][1] = sA[(rr + 8) * 40 + acol];
                    a[m2][2] = sA[rr * 40 + acol + 4];
                    a[m2][3] = sA[(rr + 8) * 40 + acol + 4];
                }
                int bro = (ks * 8 + (lane & 3)) * 136 + wn + (lane >> 2);
#pragma unroll
                for (int nt = 0; nt < 8; nt++) {
                    unsigned b0r = sB[bro + nt * 8];
                    unsigned b1r = sB[bro + 4 * 136 + nt * 8];
                    mma_tf32(acc[0][nt], a[0], b0r, b1r);
                    mma_tf32(acc[1][nt], a[1], b0r, b1r);
                }
            }
            __syncthreads();
        }
#pragma unroll
        for (int m2 = 0; m2 < 2; m2++) {
#pragma unroll
            for (int nt = 0; nt < 8; nt++) {
                int gn = wn + nt * 8 + 2 * (lane & 3);
                float bv0 = bias ? bias[gn] : 0.f;
                float bv1 = bias ? bias[gn + 1] : 0.f;
                int gm0 = bm + wm + m2 * 16 + (lane >> 2);
                if (gm0 < NN)
                    *(float2*)(out + (size_t)gm0 * 128 + gn) =
                        make_float2(acc[m2][nt][0] + bv0, acc[m2][nt][1] + bv1);
                int gm1 = gm0 + 8;
                if (gm1 < NN)
                    *(float2*)(out + (size_t)gm1 * 128 + gn) =
                        make_float2(acc[m2][nt][2] + bv0, acc[m2][nt][3] + bv1);
            }
        }
    } else if (blk < NG_BLOCKS + AT_BLOCKS) {
        int idx = (blk - NG_BLOCKS) * 256 + threadIdx.x;
        if (idx < NN * 9) {
            int n = idx / 9, j = idx % 9;
            float acc = tab[k * 9 + j];
            const float* nf = &g_nodefeat[n * 128];
            const float* W = taW + (size_t)k * 128 * 9;
#pragma unroll 8
            for (int i = 0; i < 128; i++) acc = fmaf(nf[i], W[i * 9 + j], acc);
            g_atoms[idx] = sigf(acc);
        }
    } else {
        int idx = (blk - NG_BLOCKS - AT_BLOCKS) * 256 + threadIdx.x;
        if (idx < NE * 9) g_nb[idx] = 0.f;
    }
}

// ---------------- tripacc (k=1,2 only; k=0 fused into setup1) -------------------
__global__ void k_tripacc(const int* __restrict__ t_src) {
    int t = blockIdx.x * blockDim.x + threadIdx.x;
    if (t >= NT) return;
    int es = t_src[t];
    int ea = g_endatom[t];
#pragma unroll
    for (int q = 0; q < 9; q++)
        atomicAdd(&g_nb[es * 9 + q], g_tbw[t * 9 + q] * g_atoms[ea * 9 + q]);
}

// ---------------- fused megakernel: BM=64, 512 threads (16x32 warp tile) --------
// smem bytes: sAct @0 (17408) | sAe @17408 (17408) | sB0 @34816 (17408) |
//             sB1 @52224 (17408) | swt @69632 (4608)  => 74240  (2 CTAs/SM, 32 warps)
#define FUSED_SMEM 74240
#define FUSED_GRID ((NE + 63) / 64)
#define STR 136

__global__ void __launch_bounds__(512, 2) fused_block(
    const int* __restrict__ src, const int* __restrict__ dst,
    const float* __restrict__ Wbk, const float* __restrict__ Wgk,
    const unsigned* __restrict__ wbase,                 // bf16 weights, this k (2 branches)
    const float* __restrict__ b1k, const float* __restrict__ b2k,
    const float* __restrict__ gb1k, const float* __restrict__ gb2k,
    const float* __restrict__ wtk) {
    extern __shared__ char smem_raw[];
    unsigned* sActw = (unsigned*)(smem_raw);
    unsigned* sAew  = (unsigned*)(smem_raw + 17408);
    float*    swt   = (float*)(smem_raw + 69632);

    const unsigned act_u = (unsigned)__cvta_generic_to_shared(sActw);
    const unsigned ae_u  = (unsigned)__cvta_generic_to_shared(sAew);
    const unsigned b0_u  = (unsigned)__cvta_generic_to_shared(smem_raw + 34816);
    const unsigned b1_u  = (unsigned)__cvta_generic_to_shared(smem_raw + 52224);

    const int tid = threadIdx.x;
    const int lane = tid & 31, wid = tid >> 5;   // wid 0..15
    const int wm = (wid & 3) * 16, wn = (wid >> 2) * 32;
    const int bm = blockIdx.x * 64;

    const int rr0 = wm + (lane >> 2);
    const int e0 = bm + rr0, e1 = e0 + 8;
    const bool v0 = e0 < NE, v1 = e1 < NE;
    const int s0 = v0 ? src[e0] : 0, d0 = v0 ? dst[e0] : 0;
    const int s1 = v1 ? src[e1] : 0, d1 = v1 ? dst[e1] : 0;

    // ---- stage A: three-body edge update -> g_edgefeat (fp32) + sAe (bf16) -----
    {
        float* sWb = (float*)sActw;                    // scratch (9x128)
        float* sWg = (float*)(smem_raw + 34816);       // scratch in sB0 region
        for (int i = tid; i < 9 * 128; i += 512) { sWb[i] = Wbk[i]; sWg[i] = Wgk[i]; }
        __syncthreads();
        for (int i = tid; i < 64 * 64; i += 512) {
            int row = i >> 6, cp = i & 63;
            int e = bm + row;
            float nv0 = 0.f, nv1 = 0.f;
            if (e < NE) {
                int c0 = 2 * cp;
                float s10 = 0.f, s20 = 0.f, s11 = 0.f, s21 = 0.f;
#pragma unroll
                for (int q = 0; q < 9; q++) {
                    float nv = g_nb[e * 9 + q];
                    s10 = fmaf(nv, sWb[q * 128 + c0], s10);
                    s20 = fmaf(nv, sWg[q * 128 + c0], s20);
                    s11 = fmaf(nv, sWb[q * 128 + c0 + 1], s11);
                    s21 = fmaf(nv, sWg[q * 128 + c0 + 1], s21);
                }
                float2 ef = *(const float2*)(g_edgefeat + (size_t)e * 128 + c0);
                nv0 = ef.x + siluf(s10) * sigf(s20);
                nv1 = ef.y + siluf(s11) * sigf(s21);
                *(float2*)(g_edgefeat + (size_t)e * 128 + c0) = make_float2(nv0, nv1);
            }
            sAew[row * 68 + cp] = pack_bf16(nv0, nv1);
        }
        __syncthreads();   // sWb/sWg reads done before sB0 reuse; sAe visible
    }

    float acc[4][4];
    unsigned hpk[4][2];   // silu(h2) packed bf16x2

    auto zero_acc = [&] {
#pragma unroll
        for (int j = 0; j < 4; j++)
#pragma unroll
            for (int q = 0; q < 4; q++) acc[j][q] = 0.f;
    };
    // async-copy one 64x128 bf16 weight slab (row stride 272B in smem)
    auto cp_slab = [&](const unsigned* Wb, int slab, unsigned bufu) {
#pragma unroll
        for (int i = 0; i < 2; i++) {
            int c = tid + 512 * i;
            int row = c >> 4, c4 = c & 15;
            unsigned dstb = bufu + (unsigned)(row * 272 + c4 * 16);
            const unsigned* srcp = Wb + (slab * 64 + row) * 64 + c4 * 4;
            asm volatile("cp.async.cg.shared.global [%0], [%1], 16;"
                         :: "r"(dstb), "l"(srcp) : "memory");
        }
        asm volatile("cp.async.commit_group;" ::: "memory");
    };
    auto compute_tile = [&](unsigned abase, unsigned bbase, int kbase) {
        unsigned a[4];
        {
            int arow = wm + (lane & 7) + ((lane >> 3) & 1) * 8;
            int acol = kbase + (lane >> 4) * 8;
            ldm_x4(a[0], a[1], a[2], a[3], abase + (unsigned)(arow * STR + acol) * 2);
        }
        int krow = (kbase & 63) + (lane & 15);
        int cofs = (lane >> 4) * 8;
#pragma unroll
        for (int j = 0; j < 2; j++) {
            unsigned b[4];
            int n0 = wn + 16 * j;
            ldm_x4_t(b[0], b[1], b[2], b[3], bbase + (unsigned)(krow * STR + n0 + cofs) * 2);
            mma_bf16(acc[2 * j], a, b[0], b[1]);
            mma_bf16(acc[2 * j + 1], a, b[2], b[3]);
        }
    };
    auto gemm_layer = [&](unsigned abase, const unsigned* Wb) {
        zero_acc();
        cp_slab(Wb, 0, b0_u);
        asm volatile("cp.async.wait_group 0;" ::: "memory");
        __syncthreads();
        cp_slab(Wb, 1, b1_u);
#pragma unroll
        for (int ks = 0; ks < 4; ks++) compute_tile(abase, b0_u, ks * 16);
        asm volatile("cp.async.wait_group 0;" ::: "memory");
        __syncthreads();
#pragma unroll
        for (int ks = 0; ks < 4; ks++) compute_tile(abase, b1_u, 64 + ks * 16);
        __syncthreads();
    };

    // one gated-MLP chain; leaves final raw L2 pre-activation in acc.
    auto run_chain = [&](const unsigned* wch, const float* NS, const float* ND,
                         const float* b1v) {
        gemm_layer(ae_u, wch);                      // L0 (A = edge tile)
#pragma unroll
        for (int nt = 0; nt < 4; nt++) {
            int gn = wn + nt * 8 + 2 * (lane & 3);
            float2 ns0 = v0 ? *(const float2*)(NS + (size_t)s0 * 128 + gn) : make_float2(0, 0);
            float2 nd0 = v0 ? *(const float2*)(ND + (size_t)d0 * 128 + gn) : make_float2(0, 0);
            float2 ns1 = v1 ? *(const float2*)(NS + (size_t)s1 * 128 + gn) : make_float2(0, 0);
            float2 nd1 = v1 ? *(const float2*)(ND + (size_t)d1 * 128 + gn) : make_float2(0, 0);
            sActw[rr0 * 68 + (gn >> 1)] =
                pack_bf16(siluf(acc[nt][0] + ns0.x + nd0.x), siluf(acc[nt][1] + ns0.y + nd0.y));
            sActw[(rr0 + 8) * 68 + (gn >> 1)] =
                pack_bf16(siluf(acc[nt][2] + ns1.x + nd1.x), siluf(acc[nt][3] + ns1.y + nd1.y));
        }
        gemm_layer(act_u, wch + 8192);              // L1
#pragma unroll
        for (int nt = 0; nt < 4; nt++) {
            int gn = wn + nt * 8 + 2 * (lane & 3);
            float bv0 = b1v[gn], bv1 = b1v[gn + 1];
            sActw[rr0 * 68 + (gn >> 1)] =
                pack_bf16(siluf(acc[nt][0] + bv0), siluf(acc[nt][1] + bv1));
            sActw[(rr0 + 8) * 68 + (gn >> 1)] =
                pack_bf16(siluf(acc[nt][2] + bv0), siluf(acc[nt][3] + bv1));
        }
        gemm_layer(act_u, wch + 16384);             // L2 -> raw acc
    };

    for (int br = 0; br < 2; br++) {
        const unsigned* wbr = wbase + (size_t)br * 49152;
        const float* bh1 = b1k + br * 128;
        const float* bg1 = gb1k + br * 128;
        const float* bh2 = b2k + br * 128;
        const float* bg2 = gb2k + br * 128;
        const float* NSh = g_nodepre + (size_t)(br * 4 + 0) * NN * 128;
        const float* NDh = g_nodepre + (size_t)(br * 4 + 1) * NN * 128;
        const float* NSg = g_nodepre + (size_t)(br * 4 + 2) * NN * 128;
        const float* NDg = g_nodepre + (size_t)(br * 4 + 3) * NN * 128;

        for (int i = tid; i < 9 * 128; i += 512) swt[i] = wtk[br * 9 * 128 + i];
        // ordering provided by first gemm_layer's internal barrier

        // h chain -> pack silu(h2) to bf16x2
        run_chain(wbr, NSh, NDh, bh1);
#pragma unroll
        for (int nt = 0; nt < 4; nt++) {
            int gn = wn + nt * 8 + 2 * (lane & 3);
            float bv0 = bh2[gn], bv1 = bh2[gn + 1];
            hpk[nt][0] = pack_bf16(siluf(acc[nt][0] + bv0), siluf(acc[nt][1] + bv1));
            hpk[nt][1] = pack_bf16(siluf(acc[nt][2] + bv0), siluf(acc[nt][3] + bv1));
        }
        // g chain (raw L2 in acc)
        run_chain(wbr + 24576, NSg, NDg, bg1);

        // ---- epilogue ----
        float rb0[9], rb1[9];
#pragma unroll
        for (int q = 0; q < 9; q++) {
            rb0[q] = v0 ? g_rbf[e0 * 9 + q] : 0.f;
            rb1[q] = v1 ? g_rbf[e1 * 9 + q] : 0.f;
        }
#pragma unroll
        for (int nt = 0; nt < 4; nt++) {
            int gn = wn + nt * 8 + 2 * (lane & 3);
            float w00 = 0.f, w01 = 0.f, w10 = 0.f, w11 = 0.f;
#pragma unroll
            for (int q = 0; q < 9; q++) {
                float wc0 = swt[q * 128 + gn], wc1 = swt[q * 128 + gn + 1];
                w00 = fmaf(rb0[q], wc0, w00);
                w01 = fmaf(rb0[q], wc1, w01);
                w10 = fmaf(rb1[q], wc0, w10);
                w11 = fmaf(rb1[q], wc1, w11);
            }
            float gb0v = bg2[gn], gb1v = bg2[gn + 1];
            float val0 = bf_lo(hpk[nt][0]) * sigf(acc[nt][0] + gb0v) * w00;
            float val1 = bf_hi(hpk[nt][0]) * sigf(acc[nt][1] + gb1v) * w01;
            float val2 = bf_lo(hpk[nt][1]) * sigf(acc[nt][2] + gb0v) * w10;
            float val3 = bf_hi(hpk[nt][1]) * sigf(acc[nt][3] + gb1v) * w11;
            if (br == 0) {
                if (v0) {
                    float2 base = *(const float2*)(g_edgefeat + (size_t)e0 * 128 + gn);
                    float n0v = base.x + val0, n1v = base.y + val1;
                    *(float2*)(g_edgefeat + (size_t)e0 * 128 + gn) = make_float2(n0v, n1v);
                    sAew[rr0 * 68 + (gn >> 1)] = pack_bf16(n0v, n1v);
                }
                if (v1) {
                    float2 base = *(const float2*)(g_edgefeat + (size_t)e1 * 128 + gn);
                    float n2v = base.x + val2, n3v = base.y + val3;
                    *(float2*)(g_edgefeat + (size_t)e1 * 128 + gn) = make_float2(n2v, n3v);
                    sAew[(rr0 + 8) * 68 + (gn >> 1)] = pack_bf16(n2v, n3v);
                }
            } else {
                if (v0) {
                    atomicAdd(&g_nodefeat[(size_t)d0 * 128 + gn], val0);
                    atomicAdd(&g_nodefeat[(size_t)d0 * 128 + gn + 1], val1);
                }
                if (v1) {
                    atomicAdd(&g_nodefeat[(size_t)d1 * 128 + gn], val2);
                    atomicAdd(&g_nodefeat[(size_t)d1 * 128 + gn + 1], val3);
                }
            }
        }
        __syncthreads();   // sAe update visible before br=1 L0 reads it
    }
}

// ---------------- readout -------------------------------------------------------
__global__ void k_mean() {
    int j = threadIdx.x;
    int b = blockIdx.x;
    float s = 0.f;
    for (int n = b * 125; n < b * 125 + 125; n++) s += g_nodefeat[n * 128 + j];
    atomicAdd(&g_mean[j], s);
}

__global__ void k_final(const float* __restrict__ fW0, const float* __restrict__ fb0,
                        const float* __restrict__ fW1, const float* __restrict__ fb1,
                        const float* __restrict__ fW2, const float* __restrict__ fb2,
                        float* __restrict__ out) {
    __shared__ float v[128], h0[128], h1[128], red[128];
    int j = threadIdx.x;
    v[j] = g_mean[j] / (float)NN;
    __syncthreads();
    float a = fb0[j];
    for (int i = 0; i < 128; i++) a = fmaf(v[i], fW0[i * 128 + j], a);
    h0[j] = siluf(a);
    __syncthreads();
    a = fb1[j];
    for (int i = 0; i < 128; i++) a = fmaf(h0[i], fW1[i * 128 + j], a);
    h1[j] = siluf(a);
    __syncthreads();
    red[j] = h1[j] * fW2[j];
    __syncthreads();
    for (int st = 64; st > 0; st >>= 1) {
        if (j < st) red[j] += red[j + st];
        __syncthreads();
    }
    if (j == 0) out[0] = red[0] + fb2[0];
}

// ---------------- host ----------------------------------------------------------
static double h_jl(int l, double x) {
    double s = sin(x), c = cos(x);
    if (l == 1) return s / (x * x) - c / x;
    if (l == 2) return (3.0 / (x * x * x) - 1.0 / x) * s - 3.0 * c / (x * x);
    return (15.0 / (x * x * x * x) - 6.0 / (x * x)) * s - (15.0 / (x * x * x) - 1.0 / x) * c;
}

extern "C" void kernel_launch(void* const* d_in, const int* in_sizes, int n_in,
                              void* d_out, int out_size) {
    const float* pos  = (const float*)d_in[0];
    const int* node_type = (const int*)d_in[1];
    const int* src  = (const int*)d_in[2];
    const int* dst  = (const int*)d_in[3];
    const int* t_src = (const int*)d_in[4];
    const int* t_dst = (const int*)d_in[5];
    const float* emb  = (const float*)d_in[6];
    const float* eW   = (const float*)d_in[7];
    const float* eb   = (const float*)d_in[8];
    const float* taW  = (const float*)d_in[9];
    const float* tab  = (const float*)d_in[10];
    const float* tbW  = (const float*)d_in[11];
    const float* tbWg = (const float*)d_in[12];
    const float* W0 = (const float*)d_in[13];  const float* b0 = (const float*)d_in[14];
    const float* W1 = (const float*)d_in[15];  const float* b1 = (const float*)d_in[16];
    const float* W2 = (const float*)d_in[17];  const float* b2 = (const float*)d_in[18];
    const float* gW0 = (const float*)d_in[19]; const float* gb0 = (const float*)d_in[20];
    const float* gW1 = (const float*)d_in[21]; const float* gb1 = (const float*)d_in[22];
    const float* gW2 = (const float*)d_in[23]; const float* gb2 = (const float*)d_in[24];
    const float* wt = (const float*)d_in[25];
    const float* fW0 = (const float*)d_in[26]; const float* fb0 = (const float*)d_in[27];
    const float* fW1 = (const float*)d_in[28]; const float* fb1 = (const float*)d_in[29];
    const float* fW2 = (const float*)d_in[30]; const float* fb2 = (const float*)d_in[31];
    float* out = (float*)d_out;

    Scales sc;
    {
        const double roots[9] = {
            3.141592653589793, 6.283185307179586, 9.42477796076938,
            4.493409457909064, 7.725251836937707, 10.904121659428899,
            5.763459196894550, 9.095011330476355, 12.322940970566582};
        double fac = sqrt(2.0 / 125.0);
        for (int l = 0; l < 3; l++)
            for (int n = 0; n < 3; n++)
                sc.v[l * 3 + n] = (float)(fac / fabs(h_jl(l + 1, roots[l * 3 + n])));
    }

    unsigned* pwb;
    cudaGetSymbolAddress((void**)&pwb, g_wbf16);

    cudaFuncSetAttribute(fused_block, cudaFuncAttributeMaxDynamicSharedMemorySize, FUSED_SMEM);

    int n0 = NE + NN * 128 + 128 + CONVW_N;
    k_setup0<<<(n0 + 255) / 256, 256>>>(pos, src, dst, node_type, emb, sc,
                                        W0, W1, W2, gW0, gW1, gW2);
    k_block_setup<<<NG_BLOCKS + AT_BLOCKS + ZB_BLOCKS, 256>>>(W0, gW0, b0, gb0, taW, tab, 0);
    int n1 = NT + NE * 128;
    k_setup1<<<(n1 + 255) / 256, 256>>>(t_src, t_dst, dst, eW, eb);  // includes k=0 tripacc

    for (int k = 0; k < 3; k++) {
        if (k > 0) {
            k_block_setup<<<NG_BLOCKS + AT_BLOCKS + ZB_BLOCKS, 256>>>(W0, gW0, b0, gb0, taW, tab, k);
            k_tripacc<<<(NT + 255) / 256, 256>>>(t_src);
        }
        fused_block<<<FUSED_GRID, 512, FUSED_SMEM>>>(
            src, dst, tbW + k * 9 * 128, tbWg + k * 9 * 128,
            pwb + (size_t)k * 2 * 49152,
            b1 + k * 2 * 128, b2 + k * 2 * 128,
            gb1 + k * 2 * 128, gb2 + k * 2 * 128,
            wt + k * 2 * 9 * 128);
    }
    k_mean<<<40, 128>>>();
    k_final<<<1, 128>>>(fW0, fb0, fW1, fb1, fW2, fb2, out);
}